// round 4
// baseline (speedup 1.0000x reference)
#include <cuda_runtime.h>
#include <cuda_bf16.h>
#include <cstdint>
#include <math.h>

// ============================================================================
// YOLOv3 post-processor: sigmoid -> top-4096 -> decode/clip -> greedy NMS(300)
// -> [16, 300, 6] (box4 | score | label)
// 5 kernels: keys+hist, thresh, compact, mega(sort+decode+NMS), labels
// ============================================================================

namespace yolo {

constexpr int NBATCH = 16, A = 3, H = 160, W = 160, C = 80;
constexpr int P = A * H * W;       // 76800
constexpr int HW = H * W;          // 25600
constexpr int TOPK = 4096;
constexpr int KEEP = 300;
constexpr int NBINS = 8192;        // top 13 bits of monotone score key
constexpr int CAP = 8192;
constexpr int NCHUNK = 8;          // blocks per batch in keys/compact
constexpr int CH = P / NCHUNK;     // 9600
constexpr float XCLIP = 4.135166556742356f;   // log(1000/16)
constexpr float IMGMX = 639.0f;               // 640 - TO_REMOVE

typedef unsigned long long u64;

// ---- scratch ----
__device__ uint32_t d_keys[NBATCH * P];
__device__ uint32_t d_histB[NBATCH * NCHUNK * NBINS];   // per-(batch,chunk) hist
__device__ int      d_thresh[NBATCH];
__device__ int      d_count[NBATCH];
__device__ u64      d_cand[NBATCH * CAP];
__device__ int      d_keptP[NBATCH * KEEP];   // anchor index p of kept box
__device__ int      d_keptN[NBATCH];

// monotone uint key of sigmoid(logit); sigmoid >= 0 so set the sign bit
__device__ __forceinline__ uint32_t skey(float logit) {
    float s = 1.0f / (1.0f + expf(-logit));
    return __float_as_uint(s) | 0x80000000u;
}

// ----------------------------------------------------------------------------
// keys + per-block histogram (plain stores, no zero kernel, no global atomics)
__global__ void k_keys(const float* __restrict__ obj) {
    __shared__ uint32_t sh[NBINS];
    int n = blockIdx.y, bx = blockIdx.x;
    for (int i = threadIdx.x; i < NBINS; i += blockDim.x) sh[i] = 0;
    __syncthreads();
    size_t off = (size_t)n * P + (size_t)bx * CH;
    const float* base = obj + off;
    uint32_t* kbase = d_keys + off;
    for (int i = threadIdx.x; i < CH; i += blockDim.x) {
        uint32_t k = skey(base[i]);
        kbase[i] = k;
        atomicAdd(&sh[k >> 19], 1u);
    }
    __syncthreads();
    uint32_t* hb = d_histB + (size_t)(n * NCHUNK + bx) * NBINS;
    for (int i = threadIdx.x; i < NBINS; i += blockDim.x) hb[i] = sh[i];
}

// sum sub-hists; smallest bin T with count(bins >= T) >= TOPK ; zero d_count
__global__ void k_thresh() {
    __shared__ uint32_t sh[NBINS];
    __shared__ uint32_t part[256];
    int n = blockIdx.x, t = threadIdx.x;
    const uint32_t* hb = d_histB + (size_t)n * NCHUNK * NBINS;
    for (int i = t; i < NBINS; i += 256) {
        uint32_t s = 0;
        #pragma unroll
        for (int b = 0; b < NCHUNK; b++) s += hb[(size_t)b * NBINS + i];
        sh[i] = s;
    }
    __syncthreads();
    {
        uint32_t s = 0;
        for (int b = t * 32; b < t * 32 + 32; b++) s += sh[b];
        part[t] = s;
    }
    __syncthreads();
    if (t == 0) {
        uint32_t acc = 0;
        int seg = 0;
        for (int pt = 255; pt >= 0; pt--) {
            if (acc + part[pt] >= (uint32_t)TOPK) { seg = pt; break; }
            acc += part[pt];
        }
        int T = seg * 32;
        for (int b = seg * 32 + 31; b >= seg * 32; b--) {
            acc += sh[b];
            if (acc >= (uint32_t)TOPK) { T = b; break; }
        }
        d_thresh[n] = T;
        d_count[n] = 0;
    }
}

// two-pass compact: count -> 1 global atomic per block -> coalesced warp writes
// composite key: key<<32 | (P-1-p) -> desc sort == (score desc, p asc)
// memory m = a*HW + y*W + x  ->  flattened p = (y*W+x)*A + a
__global__ __launch_bounds__(512) void k_compact() {
    __shared__ unsigned swc[16];
    __shared__ unsigned sbase[16];
    int n = blockIdx.y;
    int T = d_thresh[n];
    const uint32_t* kbase = d_keys + (size_t)n * P + (size_t)blockIdx.x * CH;
    int m0 = blockIdx.x * CH;
    const int iters = (CH + 511) / 512;   // 19
    int lane = threadIdx.x & 31, warp = threadIdx.x >> 5;

    // pass 1: count
    int cnt = 0;
    for (int it = 0; it < iters; it++) {
        int i = it * 512 + threadIdx.x;
        if (i < CH) cnt += (int)((int)(kbase[i] >> 19) >= T);
    }
    unsigned wsum = __reduce_add_sync(0xFFFFFFFFu, (unsigned)cnt);
    if (lane == 0) swc[warp] = wsum;
    __syncthreads();
    if (threadIdx.x == 0) {
        unsigned tot = 0;
        #pragma unroll
        for (int w = 0; w < 16; w++) { sbase[w] = tot; tot += swc[w]; }
        unsigned blockBase = atomicAdd((unsigned*)&d_count[n], tot);
        #pragma unroll
        for (int w = 0; w < 16; w++) sbase[w] += blockBase;
    }
    __syncthreads();

    // pass 2: write
    unsigned wbase = sbase[warp];
    u64* cand = d_cand + (size_t)n * CAP;
    for (int it = 0; it < iters; it++) {
        int i = it * 512 + threadIdx.x;
        bool sel = false;
        uint32_t key = 0;
        int p = 0;
        if (i < CH) {
            key = kbase[i];
            sel = (int)(key >> 19) >= T;
            if (sel) {
                int m = m0 + i;
                int a = m / HW;
                int rem = m - a * HW;
                p = rem * A + a;
            }
        }
        unsigned msk = __ballot_sync(0xFFFFFFFFu, sel);
        if (sel) {
            unsigned pos = wbase + __popc(msk & ((1u << lane) - 1));
            if (pos < (unsigned)CAP)
                cand[pos] = ((u64)key << 32) | (uint32_t)(P - 1 - p);
        }
        wbase += __popc(msk);
    }
}

// ----------------------------------------------------------------------------
#define CSWAP(x, y, d) { if (((x) < (y)) == (d)) { u64 _t = (x); (x) = (y); (y) = _t; } }

// mega: bitonic sort (8192) -> decode top-4096 -> greedy NMS -> output
// smem: 64KB keys + 80KB box SoA + swmin banks + keptPos  (~146KB, 1 blk/SM)
__global__ __launch_bounds__(1024, 1) void k_mega(const float* __restrict__ anchors,
                                                  const float* __restrict__ reg,
                                                  float* __restrict__ out) {
    extern __shared__ char raw[];
    u64*      s       = (u64*)raw;                    // 8192 * 8 B
    float*    sx1     = (float*)(s + CAP);            // 4096 * 4 B each
    float*    sy1     = sx1 + TOPK;
    float*    sx2     = sy1 + TOPK;
    float*    sy2     = sx2 + TOPK;
    float*    sar     = sy2 + TOPK;
    unsigned* swmin   = (unsigned*)(sar + TOPK);      // 2 banks * 32
    int*      keptPos = (int*)(swmin + 64);           // KEEP

    const int n = blockIdx.x;
    const int tid = threadIdx.x;
    const int lane = tid & 31, warp = tid >> 5;

    // ---- load candidates ----
    int cnt = min(d_count[n], CAP);
    for (int i = tid; i < CAP; i += 1024)
        s[i] = (i < cnt) ? d_cand[(size_t)n * CAP + i] : 0ULL;
    __syncthreads();

    // ---- bitonic sort, descending, register-assisted ----
    const unsigned g0s = tid * 8u;
    {
        u64 r[8];
        #pragma unroll
        for (int e = 0; e < 8; e++) r[e] = s[g0s + e];
        CSWAP(r[0], r[1], true);  CSWAP(r[2], r[3], false);
        CSWAP(r[4], r[5], true);  CSWAP(r[6], r[7], false);
        CSWAP(r[0], r[2], true);  CSWAP(r[1], r[3], true);
        CSWAP(r[4], r[6], false); CSWAP(r[5], r[7], false);
        CSWAP(r[0], r[1], true);  CSWAP(r[2], r[3], true);
        CSWAP(r[4], r[5], false); CSWAP(r[6], r[7], false);
        bool d8 = ((g0s & 8u) == 0u);
        CSWAP(r[0], r[4], d8); CSWAP(r[1], r[5], d8);
        CSWAP(r[2], r[6], d8); CSWAP(r[3], r[7], d8);
        CSWAP(r[0], r[2], d8); CSWAP(r[1], r[3], d8);
        CSWAP(r[4], r[6], d8); CSWAP(r[5], r[7], d8);
        CSWAP(r[0], r[1], d8); CSWAP(r[2], r[3], d8);
        CSWAP(r[4], r[5], d8); CSWAP(r[6], r[7], d8);
        #pragma unroll
        for (int e = 0; e < 8; e++) s[g0s + e] = r[e];
    }
    __syncthreads();

    for (unsigned k = 16; k <= (unsigned)CAP; k <<= 1) {
        for (unsigned j = k >> 1; j >= 8; j >>= 1) {
            #pragma unroll 4
            for (unsigned q = tid; q < CAP / 2; q += 1024) {
                unsigned low = q & (j - 1);
                unsigned i = ((q ^ low) << 1) | low;
                unsigned ix = i | j;
                u64 a = s[i], b = s[ix];
                bool desc = ((i & k) == 0);
                if ((a < b) == desc) { s[i] = b; s[ix] = a; }
            }
            __syncthreads();
        }
        {
            u64 r[8];
            #pragma unroll
            for (int e = 0; e < 8; e++) r[e] = s[g0s + e];
            bool d = ((g0s & k) == 0);
            CSWAP(r[0], r[4], d); CSWAP(r[1], r[5], d);
            CSWAP(r[2], r[6], d); CSWAP(r[3], r[7], d);
            CSWAP(r[0], r[2], d); CSWAP(r[1], r[3], d);
            CSWAP(r[4], r[6], d); CSWAP(r[5], r[7], d);
            CSWAP(r[0], r[1], d); CSWAP(r[2], r[3], d);
            CSWAP(r[4], r[5], d); CSWAP(r[6], r[7], d);
            #pragma unroll
            for (int e = 0; e < 8; e++) s[g0s + e] = r[e];
        }
        __syncthreads();
    }

    // ---- decode + clip top-4096 into box SoA ----
    for (int i = tid; i < TOPK; i += 1024) {
        u64 e = s[i];
        int p = P - 1 - (int)(uint32_t)e;
        int a = p % A;
        int hw = p / A;
        int y = hw / W;
        int x = hw - y * W;
        const float4 anc = *(const float4*)(anchors + ((size_t)n * P + p) * 4);
        float aw = anc.z - anc.x + 1.0f, ah = anc.w - anc.y + 1.0f;
        float acx = anc.x + 0.5f * aw,  acy = anc.y + 0.5f * ah;

        size_t rb = (size_t)((n * A + a) * 4) * HW + (size_t)y * W + x;
        float dx = __ldg(reg + rb);
        float dy = __ldg(reg + rb + HW);
        float dw = fminf(__ldg(reg + rb + 2 * (size_t)HW), XCLIP);
        float dh = fminf(__ldg(reg + rb + 3 * (size_t)HW), XCLIP);

        float pcx = dx * aw + acx, pcy = dy * ah + acy;
        float pw = expf(dw) * aw,  ph = expf(dh) * ah;
        float x1 = pcx - 0.5f * pw, y1 = pcy - 0.5f * ph;
        float x2 = pcx + 0.5f * pw - 1.0f, y2 = pcy + 0.5f * ph - 1.0f;
        x1 = fminf(fmaxf(x1, 0.0f), IMGMX);
        y1 = fminf(fmaxf(y1, 0.0f), IMGMX);
        x2 = fminf(fmaxf(x2, 0.0f), IMGMX);
        y2 = fminf(fmaxf(y2, 0.0f), IMGMX);
        sx1[i] = x1; sy1[i] = y1; sx2[i] = x2; sy2[i] = y2;
        sar[i] = (x2 - x1 + 1.0f) * (y2 - y1 + 1.0f);
    }
    __syncthreads();

    // ---- greedy NMS: 4 boxes/thread in registers, 1 barrier per pick ----
    const int g0 = tid * 4;
    float rx1[4], ry1[4], rx2[4], ry2[4], rar[4];
    #pragma unroll
    for (int e = 0; e < 4; e++) {
        rx1[e] = sx1[g0 + e]; ry1[e] = sy1[g0 + e];
        rx2[e] = sx2[g0 + e]; ry2[e] = sy2[g0 + e];
        rar[e] = sar[g0 + e];
    }

    unsigned aliveMask = 0xFu;
    unsigned ptr = 0;
    int kept = 0;
    unsigned itc = 0;

    while (ptr < (unsigned)TOPK && kept < KEEP) {
        if (tid == 0) keptPos[kept] = (int)ptr;
        kept++;
        if (aliveMask) {
            float px1 = sx1[ptr], py1 = sy1[ptr];
            float px2 = sx2[ptr], py2 = sy2[ptr], pa = sar[ptr];
            #pragma unroll
            for (int e = 0; e < 4; e++) {
                if ((aliveMask >> e) & 1u) {
                    float iw = fminf(px2, rx2[e]) - fmaxf(px1, rx1[e]) + 1.0f;
                    float ih = fminf(py2, ry2[e]) - fmaxf(py1, ry1[e]) + 1.0f;
                    iw = fmaxf(iw, 0.0f);
                    ih = fmaxf(ih, 0.0f);
                    float inter = iw * ih;
                    if (inter > 0.5f * (pa + rar[e] - inter))
                        aliveMask &= ~(1u << e);
                }
            }
        }
        unsigned cand = aliveMask ? (unsigned)(g0 + __ffs(aliveMask) - 1)
                                  : 0xFFFFFFFFu;
        unsigned wmin = __reduce_min_sync(0xFFFFFFFFu, cand);
        unsigned* bank = swmin + ((itc & 1u) << 5);
        if (lane == 0) bank[warp] = wmin;
        __syncthreads();
        // min over the 32 per-warp words (vector broadcast loads)
        unsigned mn = 0xFFFFFFFFu;
        const uint4* b4 = (const uint4*)bank;
        #pragma unroll
        for (int v = 0; v < 8; v++) {
            uint4 u = b4[v];
            mn = min(mn, min(min(u.x, u.y), min(u.z, u.w)));
        }
        ptr = mn;
        itc++;
    }

    // ---- output: boxes + scores (+label placeholder); zero invalid rows ----
    for (int k = tid; k < KEEP; k += 1024) {
        float* o = out + (size_t)(n * KEEP + k) * 6;
        if (k < kept) {
            int sidx = keptPos[k];
            uint32_t key = (uint32_t)(s[sidx] >> 32);
            int p = P - 1 - (int)(uint32_t)s[sidx];
            o[0] = sx1[sidx]; o[1] = sy1[sidx];
            o[2] = sx2[sidx]; o[3] = sy2[sidx];
            o[4] = __uint_as_float(key & 0x7FFFFFFFu);
            o[5] = 0.0f;
            d_keptP[n * KEEP + k] = p;
        } else {
            o[0] = 0.0f; o[1] = 0.0f; o[2] = 0.0f;
            o[3] = 0.0f; o[4] = 0.0f; o[5] = 0.0f;
        }
    }
    if (tid == 0) d_keptN[n] = kept;
}

// one warp per kept row: argmax over C=80 class logits, label = argmax + 1
__global__ void k_labels(const float* __restrict__ cls, float* __restrict__ out) {
    int warp_g = (blockIdx.x * blockDim.x + threadIdx.x) >> 5;
    int lane = threadIdx.x & 31;
    int nwarps = (gridDim.x * blockDim.x) >> 5;
    for (int r = warp_g; r < NBATCH * KEEP; r += nwarps) {
        int n = r / KEEP, k = r - n * KEEP;
        if (k >= d_keptN[n]) continue;
        int p = d_keptP[n * KEEP + k];
        int a = p % A;
        int hw = p / A;
        int y = hw / W;
        int x = hw - y * W;
        size_t base = (size_t)((n * A + a) * C) * HW + (size_t)y * W + x;
        float best = -INFINITY;
        int bc = 0;
        #pragma unroll 1
        for (int c = lane; c < C; c += 32) {
            float v = __ldg(cls + base + (size_t)c * HW);
            if (v > best) { best = v; bc = c; }
        }
        #pragma unroll
        for (int off = 16; off; off >>= 1) {
            float ov = __shfl_xor_sync(0xFFFFFFFFu, best, off);
            int   oc = __shfl_xor_sync(0xFFFFFFFFu, bc, off);
            if (ov > best || (ov == best && oc < bc)) { best = ov; bc = oc; }
        }
        if (lane == 0) out[(size_t)r * 6 + 5] = (float)(bc + 1);
    }
}

}  // namespace yolo

// ============================================================================
extern "C" void kernel_launch(void* const* d_in, const int* in_sizes, int n_in,
                              void* d_out, int out_size) {
    using namespace yolo;
    const float* anchors = (const float*)d_in[0];   // [16, 76800, 4]
    const float* obj     = (const float*)d_in[1];   // [16, 3, 160, 160]
    const float* reg     = (const float*)d_in[2];   // [16, 12, 160, 160]
    const float* cls     = (const float*)d_in[3];   // [16, 240, 160, 160]
    float* out = (float*)d_out;                     // [16, 300, 6]

    const int MEGA_SMEM = CAP * (int)sizeof(u64)       // 65536
                        + TOPK * 5 * (int)sizeof(float) // 81920
                        + 64 * 4 + KEEP * 4;            // 1456  => 148912

    cudaFuncSetAttribute(k_mega, cudaFuncAttributeMaxDynamicSharedMemorySize,
                         MEGA_SMEM);

    k_keys<<<dim3(NCHUNK, NBATCH), 512>>>(obj);
    k_thresh<<<NBATCH, 256>>>();
    k_compact<<<dim3(NCHUNK, NBATCH), 512>>>();
    k_mega<<<NBATCH, 1024, MEGA_SMEM>>>(anchors, reg, out);
    k_labels<<<80, 256>>>(cls, out);
}

// round 5
// speedup vs baseline: 2.6118x; 2.6118x over previous
#include <cuda_runtime.h>
#include <cstdint>
#include <math.h>

// ============================================================================
// YOLOv3 post-processor: sigmoid -> top-4096 -> decode/clip -> greedy NMS(300)
// -> [16, 300, 6] (box4 | score | label)
// kernels: hist(logit bins), thresh, compact(sigmoid keys), mega, labels
// ============================================================================

namespace yolo {

constexpr int NBATCH = 16, A = 3, H = 160, W = 160, C = 80;
constexpr int P = A * H * W;       // 76800
constexpr int HW = H * W;          // 25600
constexpr int TOPK = 4096;
constexpr int KEEP = 300;
constexpr int NBINS = 8192;        // top 13 bits of logit order-key
constexpr int CAP = 8192;
constexpr int NCHUNK = 8;
constexpr int CH = P / NCHUNK;     // 9600
constexpr float XCLIP = 4.135166556742356f;   // log(1000/16)
constexpr float IMGMX = 639.0f;               // 640 - TO_REMOVE

typedef unsigned long long u64;

// ---- scratch ----
__device__ uint32_t d_histB[NBATCH * NCHUNK * NBINS];
__device__ int      d_thresh[NBATCH];
__device__ int      d_count[NBATCH];
__device__ u64      d_cand[NBATCH * CAP];
__device__ int      d_keptP[NBATCH * KEEP];   // anchor index p of kept box
__device__ int      d_keptN[NBATCH];

// order-preserving uint key of a float (same order as the value)
__device__ __forceinline__ uint32_t lkey(float v) {
    uint32_t u = __float_as_uint(v);
    return u ^ (uint32_t)(((int)u >> 31) | 0x80000000);
}
// exact sigmoid key (sigmoid >= 0 -> set sign bit); only for candidates
__device__ __forceinline__ uint32_t skey(float logit) {
    float s = 1.0f / (1.0f + expf(-logit));
    return __float_as_uint(s) | 0x80000000u;
}

// ----------------------------------------------------------------------------
// per-(batch,chunk) histogram of logit-bin (no expf, no global atomics)
__global__ void k_hist(const float* __restrict__ obj) {
    __shared__ uint32_t sh[NBINS];
    int n = blockIdx.y, bx = blockIdx.x;
    for (int i = threadIdx.x; i < NBINS; i += blockDim.x) sh[i] = 0;
    __syncthreads();
    const float4* base = (const float4*)(obj + (size_t)n * P + (size_t)bx * CH);
    for (int i = threadIdx.x; i < CH / 4; i += blockDim.x) {
        float4 v = base[i];
        atomicAdd(&sh[lkey(v.x) >> 19], 1u);
        atomicAdd(&sh[lkey(v.y) >> 19], 1u);
        atomicAdd(&sh[lkey(v.z) >> 19], 1u);
        atomicAdd(&sh[lkey(v.w) >> 19], 1u);
    }
    __syncthreads();
    uint32_t* hb = d_histB + (size_t)(n * NCHUNK + bx) * NBINS;
    for (int i = threadIdx.x; i < NBINS; i += blockDim.x) hb[i] = sh[i];
}

// sum sub-hists; smallest bin T with count(bins >= T) >= TOPK ; zero d_count
__global__ __launch_bounds__(1024) void k_thresh() {
    __shared__ uint32_t sh[NBINS];
    __shared__ uint32_t part[256];
    int n = blockIdx.x, t = threadIdx.x;
    const uint32_t* hb = d_histB + (size_t)n * NCHUNK * NBINS;
    for (int i = t; i < NBINS; i += 1024) {
        uint32_t s = 0;
        #pragma unroll
        for (int b = 0; b < NCHUNK; b++) s += hb[(size_t)b * NBINS + i];
        sh[i] = s;
    }
    __syncthreads();
    if (t < 256) {
        uint32_t s = 0;
        for (int b = t * 32; b < t * 32 + 32; b++) s += sh[b];
        part[t] = s;
    }
    __syncthreads();
    if (t == 0) {
        uint32_t acc = 0;
        int seg = 0;
        for (int pt = 255; pt >= 0; pt--) {
            if (acc + part[pt] >= (uint32_t)TOPK) { seg = pt; break; }
            acc += part[pt];
        }
        int T = seg * 32;
        for (int b = seg * 32 + 31; b >= seg * 32; b--) {
            acc += sh[b];
            if (acc >= (uint32_t)TOPK) { T = b; break; }
        }
        d_thresh[n] = T;
        d_count[n] = 0;
    }
}

// two-pass compact: count -> 1 atomic/block -> coalesced writes.
// composite key: skey<<32 | (P-1-p) -> desc sort == (score desc, p asc)
// memory m = a*HW + y*W + x  ->  flattened p = (y*W+x)*A + a
__global__ __launch_bounds__(512) void k_compact(const float* __restrict__ obj) {
    __shared__ unsigned swc[16];
    __shared__ unsigned sbase[16];
    int n = blockIdx.y;
    int T = d_thresh[n];
    const float* base = obj + (size_t)n * P + (size_t)blockIdx.x * CH;
    int m0 = blockIdx.x * CH;
    const int iters = (CH + 511) / 512;   // 19
    int lane = threadIdx.x & 31, warp = threadIdx.x >> 5;

    int cnt = 0;
    for (int it = 0; it < iters; it++) {
        int i = it * 512 + threadIdx.x;
        if (i < CH) cnt += (int)((int)(lkey(base[i]) >> 19) >= T);
    }
    unsigned wsum = __reduce_add_sync(0xFFFFFFFFu, (unsigned)cnt);
    if (lane == 0) swc[warp] = wsum;
    __syncthreads();
    if (threadIdx.x == 0) {
        unsigned tot = 0;
        #pragma unroll
        for (int w = 0; w < 16; w++) { sbase[w] = tot; tot += swc[w]; }
        unsigned blockBase = atomicAdd((unsigned*)&d_count[n], tot);
        #pragma unroll
        for (int w = 0; w < 16; w++) sbase[w] += blockBase;
    }
    __syncthreads();

    unsigned wbase = sbase[warp];
    u64* cand = d_cand + (size_t)n * CAP;
    for (int it = 0; it < iters; it++) {
        int i = it * 512 + threadIdx.x;
        bool sel = false;
        float v = 0.0f;
        int p = 0;
        if (i < CH) {
            v = base[i];
            sel = (int)(lkey(v) >> 19) >= T;
            if (sel) {
                int m = m0 + i;
                int a = m / HW;
                int rem = m - a * HW;
                p = rem * A + a;
            }
        }
        unsigned msk = __ballot_sync(0xFFFFFFFFu, sel);
        if (sel) {
            unsigned pos = wbase + __popc(msk & ((1u << lane) - 1));
            if (pos < (unsigned)CAP)
                cand[pos] = ((u64)skey(v) << 32) | (uint32_t)(P - 1 - p);
        }
        wbase += __popc(msk);
    }
}

// ----------------------------------------------------------------------------
#define CSWAP(x, y, d) { if (((x) < (y)) == (d)) { u64 _t = (x); (x) = (y); (y) = _t; } }
#define IOU_GT(px1, py1, px2, py2, pa, qx1, qy1, qx2, qy2, qa, res) {          \
    float _iw = fminf(px2, qx2) - fmaxf(px1, qx1) + 1.0f;                      \
    float _ih = fminf(py2, qy2) - fmaxf(py1, qy1) + 1.0f;                      \
    _iw = fmaxf(_iw, 0.0f); _ih = fmaxf(_ih, 0.0f);                            \
    float _in = _iw * _ih;                                                     \
    res = _in > 0.5f * ((pa) + (qa) - _in);                                    \
}

// mega: bitonic sort (8192) -> decode top-4096 -> chunked greedy NMS -> output
__global__ __launch_bounds__(1024, 1) void k_mega(const float* __restrict__ anchors,
                                                  const float* __restrict__ reg,
                                                  float* __restrict__ out) {
    extern __shared__ char raw[];
    u64*      s    = (u64*)raw;                 // 8192*8
    float*    sx1  = (float*)(s + CAP);         // 4096*4 each
    float*    sy1  = sx1 + TOPK;
    float*    sx2  = sy1 + TOPK;
    float*    sy2  = sx2 + TOPK;
    float*    sar  = sy2 + TOPK;
    float*    kx1  = sar + TOPK;                // 304*4 each (kept list)
    float*    ky1  = kx1 + 304;
    float*    kx2  = ky1 + 304;
    float*    ky2  = kx2 + 304;
    float*    kar  = ky2 + 304;
    int*      kidx = (int*)(kar + 304);         // 304
    int*      ssup = kidx + 304;                // 32
    __shared__ int snkept;

    const int n = blockIdx.x;
    const int tid = threadIdx.x;
    const int lane = tid & 31, warp = tid >> 5;

    // ---- load candidates ----
    int cnt = min(d_count[n], CAP);
    for (int i = tid; i < CAP; i += 1024)
        s[i] = (i < cnt) ? d_cand[(size_t)n * CAP + i] : 0ULL;
    if (tid == 0) snkept = 0;
    __syncthreads();

    // ---- bitonic sort, descending, register-assisted ----
    const unsigned g0s = tid * 8u;
    {
        u64 r[8];
        #pragma unroll
        for (int e = 0; e < 8; e++) r[e] = s[g0s + e];
        CSWAP(r[0], r[1], true);  CSWAP(r[2], r[3], false);
        CSWAP(r[4], r[5], true);  CSWAP(r[6], r[7], false);
        CSWAP(r[0], r[2], true);  CSWAP(r[1], r[3], true);
        CSWAP(r[4], r[6], false); CSWAP(r[5], r[7], false);
        CSWAP(r[0], r[1], true);  CSWAP(r[2], r[3], true);
        CSWAP(r[4], r[5], false); CSWAP(r[6], r[7], false);
        bool d8 = ((g0s & 8u) == 0u);
        CSWAP(r[0], r[4], d8); CSWAP(r[1], r[5], d8);
        CSWAP(r[2], r[6], d8); CSWAP(r[3], r[7], d8);
        CSWAP(r[0], r[2], d8); CSWAP(r[1], r[3], d8);
        CSWAP(r[4], r[6], d8); CSWAP(r[5], r[7], d8);
        CSWAP(r[0], r[1], d8); CSWAP(r[2], r[3], d8);
        CSWAP(r[4], r[5], d8); CSWAP(r[6], r[7], d8);
        #pragma unroll
        for (int e = 0; e < 8; e++) s[g0s + e] = r[e];
    }
    __syncthreads();

    for (unsigned k = 16; k <= (unsigned)CAP; k <<= 1) {
        for (unsigned j = k >> 1; j >= 8; j >>= 1) {
            #pragma unroll 4
            for (unsigned q = tid; q < CAP / 2; q += 1024) {
                unsigned low = q & (j - 1);
                unsigned i = ((q ^ low) << 1) | low;
                unsigned ix = i | j;
                u64 a = s[i], b = s[ix];
                bool desc = ((i & k) == 0);
                if ((a < b) == desc) { s[i] = b; s[ix] = a; }
            }
            __syncthreads();
        }
        {
            u64 r[8];
            #pragma unroll
            for (int e = 0; e < 8; e++) r[e] = s[g0s + e];
            bool d = ((g0s & k) == 0);
            CSWAP(r[0], r[4], d); CSWAP(r[1], r[5], d);
            CSWAP(r[2], r[6], d); CSWAP(r[3], r[7], d);
            CSWAP(r[0], r[2], d); CSWAP(r[1], r[3], d);
            CSWAP(r[4], r[6], d); CSWAP(r[5], r[7], d);
            CSWAP(r[0], r[1], d); CSWAP(r[2], r[3], d);
            CSWAP(r[4], r[5], d); CSWAP(r[6], r[7], d);
            #pragma unroll
            for (int e = 0; e < 8; e++) s[g0s + e] = r[e];
        }
        __syncthreads();
    }

    // ---- decode + clip top-4096 ----
    for (int i = tid; i < TOPK; i += 1024) {
        u64 e = s[i];
        int p = P - 1 - (int)(uint32_t)e;
        int a = p % A;
        int hw = p / A;
        int y = hw / W;
        int x = hw - y * W;
        const float4 anc = *(const float4*)(anchors + ((size_t)n * P + p) * 4);
        float aw = anc.z - anc.x + 1.0f, ah = anc.w - anc.y + 1.0f;
        float acx = anc.x + 0.5f * aw,  acy = anc.y + 0.5f * ah;

        size_t rb = (size_t)((n * A + a) * 4) * HW + (size_t)y * W + x;
        float dx = __ldg(reg + rb);
        float dy = __ldg(reg + rb + HW);
        float dw = fminf(__ldg(reg + rb + 2 * (size_t)HW), XCLIP);
        float dh = fminf(__ldg(reg + rb + 3 * (size_t)HW), XCLIP);

        float pcx = dx * aw + acx, pcy = dy * ah + acy;
        float pw = expf(dw) * aw,  ph = expf(dh) * ah;
        float x1 = pcx - 0.5f * pw, y1 = pcy - 0.5f * ph;
        float x2 = pcx + 0.5f * pw - 1.0f, y2 = pcy + 0.5f * ph - 1.0f;
        x1 = fminf(fmaxf(x1, 0.0f), IMGMX);
        y1 = fminf(fmaxf(y1, 0.0f), IMGMX);
        x2 = fminf(fmaxf(x2, 0.0f), IMGMX);
        y2 = fminf(fmaxf(y2, 0.0f), IMGMX);
        sx1[i] = x1; sy1[i] = y1; sx2[i] = x2; sy2[i] = y2;
        sar[i] = (x2 - x1 + 1.0f) * (y2 - y1 + 1.0f);
    }
    __syncthreads();

    // ---- chunked greedy NMS: test chunk vs kept list, then serial resolve ----
    for (int c = 0; c < TOPK / 32; c++) {
        int nk = snkept;
        if (nk >= KEEP) break;

        // phase 1: warp w tests chunk box (32c + w) against kept list
        int bi = c * 32 + warp;
        float bx1 = sx1[bi], by1 = sy1[bi], bx2 = sx2[bi], by2 = sy2[bi];
        float ba = sar[bi];
        bool sup = false;
        for (int t = lane; t < nk; t += 32) {
            bool o;
            IOU_GT(bx1, by1, bx2, by2, ba, kx1[t], ky1[t], kx2[t], ky2[t], kar[t], o);
            sup |= o;
        }
        unsigned any = __ballot_sync(0xFFFFFFFFu, sup);
        if (lane == 0) ssup[warp] = (any != 0);
        __syncthreads();

        // phase 2: warp 0 resolves the chunk serially (lane l owns box 32c+l)
        if (warp == 0) {
            int mybi = c * 32 + lane;
            float mx1 = sx1[mybi], my1 = sy1[mybi];
            float mx2 = sx2[mybi], my2 = sy2[mybi], ma = sar[mybi];
            bool presup = ssup[lane] != 0;
            unsigned dead = __ballot_sync(0xFFFFFFFFu, presup);
            unsigned pickmask = 0;
            int navail = KEEP - nk;
            int np = 0;
            for (int k = 0; k < 32; k++) {
                if (!((dead >> k) & 1u)) {
                    pickmask |= 1u << k;
                    np++;
                    float px1 = __shfl_sync(0xFFFFFFFFu, mx1, k);
                    float py1 = __shfl_sync(0xFFFFFFFFu, my1, k);
                    float px2 = __shfl_sync(0xFFFFFFFFu, mx2, k);
                    float py2 = __shfl_sync(0xFFFFFFFFu, my2, k);
                    float pa  = __shfl_sync(0xFFFFFFFFu, ma, k);
                    bool o;
                    IOU_GT(px1, py1, px2, py2, pa, mx1, my1, mx2, my2, ma, o);
                    dead |= __ballot_sync(0xFFFFFFFFu, o);
                    if (np == navail) break;
                }
            }
            if ((pickmask >> lane) & 1u) {
                int pos = nk + __popc(pickmask & ((1u << lane) - 1u));
                kx1[pos] = mx1; ky1[pos] = my1;
                kx2[pos] = mx2; ky2[pos] = my2;
                kar[pos] = ma;  kidx[pos] = mybi;
            }
            if (lane == 0) snkept = nk + np;
        }
        __syncthreads();
    }

    // ---- output ----
    int kept = snkept;
    for (int k = tid; k < KEEP; k += 1024) {
        float* o = out + (size_t)(n * KEEP + k) * 6;
        if (k < kept) {
            int sidx = kidx[k];
            u64 e = s[sidx];
            o[0] = kx1[k]; o[1] = ky1[k]; o[2] = kx2[k]; o[3] = ky2[k];
            o[4] = __uint_as_float((uint32_t)(e >> 32) & 0x7FFFFFFFu);
            o[5] = 0.0f;
            d_keptP[n * KEEP + k] = P - 1 - (int)(uint32_t)e;
        } else {
            o[0] = 0.0f; o[1] = 0.0f; o[2] = 0.0f;
            o[3] = 0.0f; o[4] = 0.0f; o[5] = 0.0f;
        }
    }
    if (tid == 0) d_keptN[n] = kept;
}

// one warp per kept row: argmax over C=80 class logits, label = argmax + 1
__global__ void k_labels(const float* __restrict__ cls, float* __restrict__ out) {
    int warp_g = (blockIdx.x * blockDim.x + threadIdx.x) >> 5;
    int lane = threadIdx.x & 31;
    int nwarps = (gridDim.x * blockDim.x) >> 5;
    for (int r = warp_g; r < NBATCH * KEEP; r += nwarps) {
        int n = r / KEEP, k = r - n * KEEP;
        if (k >= d_keptN[n]) continue;
        int p = d_keptP[n * KEEP + k];
        int a = p % A;
        int hw = p / A;
        int y = hw / W;
        int x = hw - y * W;
        size_t base = (size_t)((n * A + a) * C) * HW + (size_t)y * W + x;
        float best = -INFINITY;
        int bc = 0;
        #pragma unroll 1
        for (int c = lane; c < C; c += 32) {
            float v = __ldg(cls + base + (size_t)c * HW);
            if (v > best) { best = v; bc = c; }
        }
        #pragma unroll
        for (int off = 16; off; off >>= 1) {
            float ov = __shfl_xor_sync(0xFFFFFFFFu, best, off);
            int   oc = __shfl_xor_sync(0xFFFFFFFFu, bc, off);
            if (ov > best || (ov == best && oc < bc)) { best = ov; bc = oc; }
        }
        if (lane == 0) out[(size_t)r * 6 + 5] = (float)(bc + 1);
    }
}

}  // namespace yolo

// ============================================================================
extern "C" void kernel_launch(void* const* d_in, const int* in_sizes, int n_in,
                              void* d_out, int out_size) {
    using namespace yolo;
    const float* anchors = (const float*)d_in[0];   // [16, 76800, 4]
    const float* obj     = (const float*)d_in[1];   // [16, 3, 160, 160]
    const float* reg     = (const float*)d_in[2];   // [16, 12, 160, 160]
    const float* cls     = (const float*)d_in[3];   // [16, 240, 160, 160]
    float* out = (float*)d_out;                     // [16, 300, 6]

    const int MEGA_SMEM = CAP * (int)sizeof(u64)        // 65536
                        + TOPK * 5 * (int)sizeof(float) // 81920
                        + 304 * 6 * 4 + 32 * 4;         // 7424  => 154880

    cudaFuncSetAttribute(k_mega, cudaFuncAttributeMaxDynamicSharedMemorySize,
                         MEGA_SMEM);

    k_hist<<<dim3(NCHUNK, NBATCH), 512>>>(obj);
    k_thresh<<<NBATCH, 1024>>>();
    k_compact<<<dim3(NCHUNK, NBATCH), 512>>>(obj);
    k_mega<<<NBATCH, 1024, MEGA_SMEM>>>(anchors, reg, out);
    k_labels<<<80, 256>>>(cls, out);
}

// round 6
// speedup vs baseline: 3.7172x; 1.4232x over previous
#include <cuda_runtime.h>
#include <cstdint>
#include <math.h>

// ============================================================================
// YOLOv3 post-processor: sigmoid -> top-4096 -> decode/clip -> greedy NMS(300)
// -> [16, 300, 6] (box4 | score | label)
// kernels: hist, thresh(+deterministic slot bases), compact(+decode), mega, labels
// ============================================================================

namespace yolo {

constexpr int NBATCH = 16, A = 3, H = 160, W = 160, C = 80;
constexpr int P = A * H * W;       // 76800
constexpr int HW = H * W;          // 25600
constexpr int TOPK = 4096;
constexpr int KEEP = 300;
constexpr int NBINS = 8192;        // top 13 bits of logit order-key
constexpr int NCHUNK = 8;
constexpr int CH = P / NCHUNK;     // 9600
constexpr float XCLIP = 4.135166556742356f;   // log(1000/16)
constexpr float IMGMX = 639.0f;               // 640 - TO_REMOVE

typedef unsigned long long u64;

// ---- scratch ----
__device__ uint32_t d_histB[NBATCH * NCHUNK * NBINS];
__device__ int      d_thresh[NBATCH];
__device__ uint32_t d_hiBase[NBATCH * NCHUNK];
__device__ uint32_t d_tBase[NBATCH * NCHUNK];
__device__ u64      d_ckeys[NBATCH * TOPK];
__device__ float4   d_cbox[NBATCH * TOPK];
__device__ int      d_keptP[NBATCH * KEEP];
__device__ int      d_keptN[NBATCH];

// order-preserving uint key of a float
__device__ __forceinline__ uint32_t lkey(float v) {
    uint32_t u = __float_as_uint(v);
    return u ^ (uint32_t)(((int)u >> 31) | 0x80000000);
}
// exact sigmoid key (sigmoid >= 0 -> set sign bit); candidates only
__device__ __forceinline__ uint32_t skey(float logit) {
    float s = 1.0f / (1.0f + expf(-logit));
    return __float_as_uint(s) | 0x80000000u;
}

// ----------------------------------------------------------------------------
__global__ void k_hist(const float* __restrict__ obj) {
    __shared__ uint32_t sh[NBINS];
    int n = blockIdx.y, bx = blockIdx.x;
    for (int i = threadIdx.x; i < NBINS; i += blockDim.x) sh[i] = 0;
    __syncthreads();
    const float4* base = (const float4*)(obj + (size_t)n * P + (size_t)bx * CH);
    for (int i = threadIdx.x; i < CH / 4; i += blockDim.x) {
        float4 v = base[i];
        atomicAdd(&sh[lkey(v.x) >> 19], 1u);
        atomicAdd(&sh[lkey(v.y) >> 19], 1u);
        atomicAdd(&sh[lkey(v.z) >> 19], 1u);
        atomicAdd(&sh[lkey(v.w) >> 19], 1u);
    }
    __syncthreads();
    uint32_t* hb = d_histB + (size_t)(n * NCHUNK + bx) * NBINS;
    for (int i = threadIdx.x; i < NBINS; i += blockDim.x) hb[i] = sh[i];
}

// threshold T + deterministic per-chunk slot bases (no atomics anywhere)
__global__ __launch_bounds__(1024) void k_thresh() {
    __shared__ uint32_t sh[NBINS];
    __shared__ uint32_t part[256];
    __shared__ uint32_t hiCnt[NCHUNK], tCnt[NCHUNK];
    __shared__ int sT;
    int n = blockIdx.x, t = threadIdx.x;
    const uint32_t* hb = d_histB + (size_t)n * NCHUNK * NBINS;
    for (int i = t; i < NBINS; i += 1024) {
        uint32_t s = 0;
        #pragma unroll
        for (int b = 0; b < NCHUNK; b++) s += hb[(size_t)b * NBINS + i];
        sh[i] = s;
    }
    __syncthreads();
    if (t < 256) {
        uint32_t s = 0;
        for (int b = t * 32; b < t * 32 + 32; b++) s += sh[b];
        part[t] = s;
    }
    __syncthreads();
    if (t == 0) {
        uint32_t acc = 0;
        int seg = 0;
        for (int pt = 255; pt >= 0; pt--) {
            if (acc + part[pt] >= (uint32_t)TOPK) { seg = pt; break; }
            acc += part[pt];
        }
        int T = seg * 32;
        for (int b = seg * 32 + 31; b >= seg * 32; b--) {
            acc += sh[b];
            if (acc >= (uint32_t)TOPK) { T = b; break; }
        }
        sT = T;
    }
    __syncthreads();
    int T = sT;
    int warp = t >> 5, lane = t & 31;
    if (warp < NCHUNK) {
        uint32_t s = 0;
        for (int b = T + 1 + lane; b < NBINS; b += 32)
            s += hb[(size_t)warp * NBINS + b];
        s = __reduce_add_sync(0xFFFFFFFFu, s);
        if (lane == 0) {
            hiCnt[warp] = s;
            tCnt[warp] = hb[(size_t)warp * NBINS + T];
        }
    }
    __syncthreads();
    if (t == 0) {
        uint32_t acc = 0;
        #pragma unroll
        for (int c = 0; c < NCHUNK; c++) { d_hiBase[n * NCHUNK + c] = acc; acc += hiCnt[c]; }
        uint32_t tb = acc;                     // totalHi
        #pragma unroll
        for (int c = 0; c < NCHUNK; c++) { d_tBase[n * NCHUNK + c] = tb; tb += tCnt[c]; }
        d_thresh[n] = T;
    }
}

// compact + decode into exact TOPK deterministic slots.
// key = skey<<32 | (P-1-p)<<15 | slot  (order = score desc, p asc)
__global__ __launch_bounds__(512) void k_compact(const float* __restrict__ obj,
                                                 const float* __restrict__ anchors,
                                                 const float* __restrict__ reg) {
    __shared__ unsigned whi[16], wtq[16], bhi[16], btq[16];
    int n = blockIdx.y, bx = blockIdx.x;
    int T = d_thresh[n];
    const float* base = obj + (size_t)n * P + (size_t)bx * CH;
    int m0 = bx * CH;
    const int iters = (CH + 511) / 512;   // 19
    int lane = threadIdx.x & 31, warp = threadIdx.x >> 5;

    // pass 1: per-warp counts
    int chi = 0, ctq = 0;
    for (int it = 0; it < iters; it++) {
        int i = it * 512 + threadIdx.x;
        if (i < CH) {
            int b = (int)(lkey(base[i]) >> 19);
            chi += (b > T);
            ctq += (b == T);
        }
    }
    unsigned shi = __reduce_add_sync(0xFFFFFFFFu, (unsigned)chi);
    unsigned stq = __reduce_add_sync(0xFFFFFFFFu, (unsigned)ctq);
    if (lane == 0) { whi[warp] = shi; wtq[warp] = stq; }
    __syncthreads();
    if (threadIdx.x == 0) {
        unsigned h = d_hiBase[n * NCHUNK + bx];
        unsigned tb = d_tBase[n * NCHUNK + bx];
        #pragma unroll
        for (int w = 0; w < 16; w++) { bhi[w] = h; h += whi[w]; btq[w] = tb; tb += wtq[w]; }
    }
    __syncthreads();

    // pass 2: deterministic placement + decode
    unsigned hibase = bhi[warp], tqbase = btq[warp];
    u64*    ckeys = d_ckeys + (size_t)n * TOPK;
    float4* cbox  = d_cbox  + (size_t)n * TOPK;
    for (int it = 0; it < iters; it++) {
        int i = it * 512 + threadIdx.x;
        bool hi = false, tq = false;
        float v = 0.0f;
        if (i < CH) {
            v = base[i];
            int b = (int)(lkey(v) >> 19);
            hi = (b > T);
            tq = (b == T);
        }
        unsigned mhi = __ballot_sync(0xFFFFFFFFu, hi);
        unsigned mtq = __ballot_sync(0xFFFFFFFFu, tq);
        unsigned slot = 0;
        bool wr = false;
        if (hi) { slot = hibase + __popc(mhi & ((1u << lane) - 1)); wr = true; }
        else if (tq) {
            slot = tqbase + __popc(mtq & ((1u << lane) - 1));
            wr = slot < (unsigned)TOPK;
        }
        hibase += __popc(mhi);
        tqbase += __popc(mtq);
        if (wr) {
            int m = m0 + i;
            int a = m / HW;
            int rem = m - a * HW;            // y*W + x
            int p = rem * A + a;
            ckeys[slot] = ((u64)skey(v) << 32) | ((u64)(uint32_t)(P - 1 - p) << 15)
                        | (u64)slot;
            // decode + clip
            int y = rem / W;
            int x = rem - y * W;
            const float4 anc = *(const float4*)(anchors + ((size_t)n * P + p) * 4);
            float aw = anc.z - anc.x + 1.0f, ah = anc.w - anc.y + 1.0f;
            float acx = anc.x + 0.5f * aw,  acy = anc.y + 0.5f * ah;
            size_t rb = (size_t)((n * A + a) * 4) * HW + (size_t)rem;
            float dx = __ldg(reg + rb);
            float dy = __ldg(reg + rb + HW);
            float dw = fminf(__ldg(reg + rb + 2 * (size_t)HW), XCLIP);
            float dh = fminf(__ldg(reg + rb + 3 * (size_t)HW), XCLIP);
            float pcx = dx * aw + acx, pcy = dy * ah + acy;
            float pw = expf(dw) * aw,  ph = expf(dh) * ah;
            float x1 = pcx - 0.5f * pw, y1 = pcy - 0.5f * ph;
            float x2 = pcx + 0.5f * pw - 1.0f, y2 = pcy + 0.5f * ph - 1.0f;
            x1 = fminf(fmaxf(x1, 0.0f), IMGMX);
            y1 = fminf(fmaxf(y1, 0.0f), IMGMX);
            x2 = fminf(fmaxf(x2, 0.0f), IMGMX);
            y2 = fminf(fmaxf(y2, 0.0f), IMGMX);
            cbox[slot] = make_float4(x1, y1, x2, y2);
        }
    }
}

// ----------------------------------------------------------------------------
#define CSWAP(x, y, d) { if (((x) < (y)) == (d)) { u64 _t = (x); (x) = (y); (y) = _t; } }
#define IOU_GT(px1, py1, px2, py2, pa, qx1, qy1, qx2, qy2, qa, res) {          \
    float _iw = fminf(px2, qx2) - fmaxf(px1, qx1) + 1.0f;                      \
    float _ih = fminf(py2, qy2) - fmaxf(py1, qy1) + 1.0f;                      \
    _iw = fmaxf(_iw, 0.0f); _ih = fmaxf(_ih, 0.0f);                            \
    float _in = _iw * _ih;                                                     \
    res = _in > 0.5f * ((pa) + (qa) - _in);                                    \
}

__device__ __forceinline__ void shfl_pass(u64* r, unsigned jl, bool d, unsigned tid) {
    bool upper = (tid & jl) != 0;
    bool keepMax = (d != upper);
    #pragma unroll
    for (int e = 0; e < 4; e++) {
        u64 v = __shfl_xor_sync(0xFFFFFFFFu, r[e], jl);
        r[e] = keepMax ? (r[e] > v ? r[e] : v) : (r[e] < v ? r[e] : v);
    }
}

// mega: shfl-bitonic sort of 4096 keys -> chunked greedy NMS -> output
__global__ __launch_bounds__(1024, 1) void k_mega(float* __restrict__ out) {
    extern __shared__ char raw[];
    u64*   s    = (u64*)raw;                 // 4096*8
    float* sx1  = (float*)(s + TOPK);        // 4096*4 each
    float* sy1  = sx1 + TOPK;
    float* sx2  = sy1 + TOPK;
    float* sy2  = sx2 + TOPK;
    float* sar  = sy2 + TOPK;
    float* kx1  = sar + TOPK;                // kept list, 304 each
    float* ky1  = kx1 + 304;
    float* kx2  = ky1 + 304;
    float* ky2  = kx2 + 304;
    float* kar  = ky2 + 304;
    float* ksc  = kar + 304;
    int*   kp   = (int*)(ksc + 304);
    int*   ssup = kp + 304;                  // 32
    __shared__ int snkept;

    const int n = blockIdx.x;
    const int tid = threadIdx.x;
    const int lane = tid & 31, warp = tid >> 5;

    // ---- load keys + boxes ----
    for (int i = tid; i < TOPK; i += 1024) {
        s[i] = d_ckeys[(size_t)n * TOPK + i];
        float4 b = d_cbox[(size_t)n * TOPK + i];
        sx1[i] = b.x; sy1[i] = b.y; sx2[i] = b.z; sy2[i] = b.w;
        sar[i] = (b.z - b.x + 1.0f) * (b.w - b.y + 1.0f);
    }
    if (tid == 0) snkept = 0;
    __syncthreads();

    // ---- bitonic sort (descending), 4 elems/thread, shfl for j<=64 ----
    const unsigned g0 = tid * 4u;
    u64 r[4];
    {
        #pragma unroll
        for (int e = 0; e < 4; e++) r[e] = s[g0 + e];
        CSWAP(r[0], r[1], true);  CSWAP(r[2], r[3], false);
        {
            bool d = ((g0 & 4u) == 0u);
            CSWAP(r[0], r[2], d); CSWAP(r[1], r[3], d);
            CSWAP(r[0], r[1], d); CSWAP(r[2], r[3], d);
        }
        #pragma unroll
        for (unsigned k = 8; k <= 128; k <<= 1) {
            bool d = ((g0 & k) == 0u);
            for (unsigned j = k >> 1; j >= 4; j >>= 1)
                shfl_pass(r, j >> 2, d, tid);
            CSWAP(r[0], r[2], d); CSWAP(r[1], r[3], d);
            CSWAP(r[0], r[1], d); CSWAP(r[2], r[3], d);
        }
        #pragma unroll
        for (int e = 0; e < 4; e++) s[g0 + e] = r[e];
    }
    __syncthreads();

    for (unsigned k = 256; k <= (unsigned)TOPK; k <<= 1) {
        for (unsigned j = k >> 1; j >= 128; j >>= 1) {
            for (unsigned q = tid; q < TOPK / 2; q += 1024) {
                unsigned low = q & (j - 1);
                unsigned i = ((q ^ low) << 1) | low;
                unsigned ix = i | j;
                u64 a = s[i], b = s[ix];
                bool desc = ((i & k) == 0);
                if ((a < b) == desc) { s[i] = b; s[ix] = a; }
            }
            __syncthreads();
        }
        {
            #pragma unroll
            for (int e = 0; e < 4; e++) r[e] = s[g0 + e];
            bool d = ((g0 & k) == 0u);
            for (unsigned j = 64; j >= 4; j >>= 1)
                shfl_pass(r, j >> 2, d, tid);
            CSWAP(r[0], r[2], d); CSWAP(r[1], r[3], d);
            CSWAP(r[0], r[1], d); CSWAP(r[2], r[3], d);
            #pragma unroll
            for (int e = 0; e < 4; e++) s[g0 + e] = r[e];
        }
        __syncthreads();
    }

    // ---- chunked greedy NMS (test vs kept list, then serial resolve) ----
    for (int c = 0; c < TOPK / 32; c++) {
        int nk = snkept;
        if (nk >= KEEP) break;

        // phase 1: warp w tests sorted box (32c+w) against kept list
        {
            unsigned slot = (unsigned)s[c * 32 + warp] & 0xFFFu;
            float bx1 = sx1[slot], by1 = sy1[slot];
            float bx2 = sx2[slot], by2 = sy2[slot], ba = sar[slot];
            bool sup = false;
            for (int t = lane; t < nk; t += 32) {
                bool o;
                IOU_GT(bx1, by1, bx2, by2, ba, kx1[t], ky1[t], kx2[t], ky2[t], kar[t], o);
                sup |= o;
            }
            unsigned any = __ballot_sync(0xFFFFFFFFu, sup);
            if (lane == 0) ssup[warp] = (any != 0);
        }
        __syncthreads();

        // phase 2: warp 0 resolves the chunk serially (lane l owns box 32c+l)
        if (warp == 0) {
            u64 key = s[c * 32 + lane];
            unsigned slot = (unsigned)key & 0xFFFu;
            float mx1 = sx1[slot], my1 = sy1[slot];
            float mx2 = sx2[slot], my2 = sy2[slot], ma = sar[slot];
            unsigned aliveM = ~__ballot_sync(0xFFFFFFFFu, ssup[lane] != 0);
            unsigned pickmask = 0;
            int navail = KEEP - nk;
            int np = 0;
            while (aliveM && np < navail) {
                int kk = __ffs(aliveM) - 1;
                pickmask |= 1u << kk;
                np++;
                float px1 = __shfl_sync(0xFFFFFFFFu, mx1, kk);
                float py1 = __shfl_sync(0xFFFFFFFFu, my1, kk);
                float px2 = __shfl_sync(0xFFFFFFFFu, mx2, kk);
                float py2 = __shfl_sync(0xFFFFFFFFu, my2, kk);
                float pa  = __shfl_sync(0xFFFFFFFFu, ma, kk);
                bool o;
                IOU_GT(px1, py1, px2, py2, pa, mx1, my1, mx2, my2, ma, o);
                aliveM &= ~__ballot_sync(0xFFFFFFFFu, o);
                aliveM &= ~(1u << kk);
            }
            if ((pickmask >> lane) & 1u) {
                int pos = nk + __popc(pickmask & ((1u << lane) - 1u));
                kx1[pos] = mx1; ky1[pos] = my1;
                kx2[pos] = mx2; ky2[pos] = my2;
                kar[pos] = ma;
                ksc[pos] = __uint_as_float((uint32_t)(key >> 32) & 0x7FFFFFFFu);
                kp[pos]  = P - 1 - (int)(((uint32_t)key >> 15) & 0x1FFFFu);
            }
            if (lane == 0) snkept = nk + np;
        }
        __syncthreads();
    }

    // ---- output ----
    int kept = snkept;
    for (int k = tid; k < KEEP; k += 1024) {
        float* o = out + (size_t)(n * KEEP + k) * 6;
        if (k < kept) {
            o[0] = kx1[k]; o[1] = ky1[k]; o[2] = kx2[k]; o[3] = ky2[k];
            o[4] = ksc[k];
            o[5] = 0.0f;
            d_keptP[n * KEEP + k] = kp[k];
        } else {
            o[0] = 0.0f; o[1] = 0.0f; o[2] = 0.0f;
            o[3] = 0.0f; o[4] = 0.0f; o[5] = 0.0f;
        }
    }
    if (tid == 0) d_keptN[n] = kept;
}

// one warp per kept row: argmax over C=80 class logits, label = argmax + 1
__global__ void k_labels(const float* __restrict__ cls, float* __restrict__ out) {
    int warp_g = (blockIdx.x * blockDim.x + threadIdx.x) >> 5;
    int lane = threadIdx.x & 31;
    int nwarps = (gridDim.x * blockDim.x) >> 5;
    for (int r = warp_g; r < NBATCH * KEEP; r += nwarps) {
        int n = r / KEEP, k = r - n * KEEP;
        if (k >= d_keptN[n]) continue;
        int p = d_keptP[n * KEEP + k];
        int a = p % A;
        int hw = p / A;
        size_t base = (size_t)((n * A + a) * C) * HW + (size_t)hw;
        float best = -INFINITY;
        int bc = 0;
        for (int c = lane; c < C; c += 32) {
            float v = __ldg(cls + base + (size_t)c * HW);
            if (v > best) { best = v; bc = c; }
        }
        #pragma unroll
        for (int off = 16; off; off >>= 1) {
            float ov = __shfl_xor_sync(0xFFFFFFFFu, best, off);
            int   oc = __shfl_xor_sync(0xFFFFFFFFu, bc, off);
            if (ov > best || (ov == best && oc < bc)) { best = ov; bc = oc; }
        }
        if (lane == 0) out[(size_t)r * 6 + 5] = (float)(bc + 1);
    }
}

}  // namespace yolo

// ============================================================================
extern "C" void kernel_launch(void* const* d_in, const int* in_sizes, int n_in,
                              void* d_out, int out_size) {
    using namespace yolo;
    const float* anchors = (const float*)d_in[0];   // [16, 76800, 4]
    const float* obj     = (const float*)d_in[1];   // [16, 3, 160, 160]
    const float* reg     = (const float*)d_in[2];   // [16, 12, 160, 160]
    const float* cls     = (const float*)d_in[3];   // [16, 240, 160, 160]
    float* out = (float*)d_out;                     // [16, 300, 6]

    const int MEGA_SMEM = TOPK * (int)sizeof(u64)       // 32768
                        + TOPK * 5 * (int)sizeof(float) // 81920
                        + 304 * 7 * 4 + 32 * 4;         // 8640  => 123328

    cudaFuncSetAttribute(k_mega, cudaFuncAttributeMaxDynamicSharedMemorySize,
                         MEGA_SMEM);

    k_hist<<<dim3(NCHUNK, NBATCH), 512>>>(obj);
    k_thresh<<<NBATCH, 1024>>>();
    k_compact<<<dim3(NCHUNK, NBATCH), 512>>>(obj, anchors, reg);
    k_mega<<<NBATCH, 1024, MEGA_SMEM>>>(out);
    k_labels<<<150, 256>>>(cls, out);
}

// round 7
// speedup vs baseline: 3.8637x; 1.0394x over previous
#include <cuda_runtime.h>
#include <cstdint>
#include <math.h>

// ============================================================================
// YOLOv3 post-processor: sigmoid -> top-4096 -> decode/clip -> greedy NMS(300)
// -> [16, 300, 6] (box4 | score | label)
// kernels: hist, thresh(+slot bases), compact(+decode), mega(sort+NMS+labels)
// ============================================================================

namespace yolo {

constexpr int NBATCH = 16, A = 3, H = 160, W = 160, C = 80;
constexpr int P = A * H * W;       // 76800
constexpr int HW = H * W;          // 25600
constexpr int TOPK = 4096;
constexpr int KEEP = 300;
constexpr int NBINS = 2048;        // top 11 bits of logit order-key
constexpr int SHIFT = 21;          // 32 - 11
constexpr int NCHUNK = 8;
constexpr int CH = P / NCHUNK;     // 9600
constexpr float XCLIP = 4.135166556742356f;   // log(1000/16)
constexpr float IMGMX = 639.0f;               // 640 - TO_REMOVE

typedef unsigned long long u64;

// ---- scratch ----
__device__ uint32_t d_histB[NBATCH * NCHUNK * NBINS];
__device__ int      d_thresh[NBATCH];
__device__ uint32_t d_hiBase[NBATCH * NCHUNK];
__device__ uint32_t d_tBase[NBATCH * NCHUNK];
__device__ u64      d_ckeys[NBATCH * TOPK];
__device__ float4   d_cbox[NBATCH * TOPK];

// order-preserving uint key of a float
__device__ __forceinline__ uint32_t lkey(float v) {
    uint32_t u = __float_as_uint(v);
    return u ^ (uint32_t)(((int)u >> 31) | 0x80000000);
}
// exact sigmoid key (sigmoid >= 0 -> set sign bit); candidates only
__device__ __forceinline__ uint32_t skey(float logit) {
    float s = 1.0f / (1.0f + expf(-logit));
    return __float_as_uint(s) | 0x80000000u;
}

// ----------------------------------------------------------------------------
__global__ void k_hist(const float* __restrict__ obj) {
    __shared__ uint32_t sh[NBINS];
    int n = blockIdx.y, bx = blockIdx.x;
    for (int i = threadIdx.x; i < NBINS; i += blockDim.x) sh[i] = 0;
    __syncthreads();
    const float4* base = (const float4*)(obj + (size_t)n * P + (size_t)bx * CH);
    for (int i = threadIdx.x; i < CH / 4; i += blockDim.x) {
        float4 v = base[i];
        atomicAdd(&sh[lkey(v.x) >> SHIFT], 1u);
        atomicAdd(&sh[lkey(v.y) >> SHIFT], 1u);
        atomicAdd(&sh[lkey(v.z) >> SHIFT], 1u);
        atomicAdd(&sh[lkey(v.w) >> SHIFT], 1u);
    }
    __syncthreads();
    uint32_t* hb = d_histB + (size_t)(n * NCHUNK + bx) * NBINS;
    for (int i = threadIdx.x; i < NBINS; i += blockDim.x) hb[i] = sh[i];
}

// threshold T + deterministic per-chunk slot bases (no atomics)
__global__ __launch_bounds__(256) void k_thresh() {
    __shared__ uint32_t sh[NBINS];
    __shared__ uint32_t part[64];
    __shared__ uint32_t hiCnt[NCHUNK], tCnt[NCHUNK];
    __shared__ int sT;
    int n = blockIdx.x, t = threadIdx.x;
    const uint32_t* hb = d_histB + (size_t)n * NCHUNK * NBINS;
    for (int i = t; i < NBINS; i += 256) {
        uint32_t s = 0;
        #pragma unroll
        for (int b = 0; b < NCHUNK; b++) s += hb[(size_t)b * NBINS + i];
        sh[i] = s;
    }
    __syncthreads();
    if (t < 64) {
        uint32_t s = 0;
        for (int b = t * 32; b < t * 32 + 32; b++) s += sh[b];
        part[t] = s;
    }
    __syncthreads();
    if (t == 0) {
        uint32_t acc = 0;
        int seg = 0;
        for (int pt = 63; pt >= 0; pt--) {
            if (acc + part[pt] >= (uint32_t)TOPK) { seg = pt; break; }
            acc += part[pt];
        }
        int T = seg * 32;
        for (int b = seg * 32 + 31; b >= seg * 32; b--) {
            acc += sh[b];
            if (acc >= (uint32_t)TOPK) { T = b; break; }
        }
        sT = T;
    }
    __syncthreads();
    int T = sT;
    int warp = t >> 5, lane = t & 31;
    if (warp < NCHUNK) {
        uint32_t s = 0;
        for (int b = T + 1 + lane; b < NBINS; b += 32)
            s += hb[(size_t)warp * NBINS + b];
        s = __reduce_add_sync(0xFFFFFFFFu, s);
        if (lane == 0) {
            hiCnt[warp] = s;
            tCnt[warp] = hb[(size_t)warp * NBINS + T];
        }
    }
    __syncthreads();
    if (t == 0) {
        uint32_t acc = 0;
        #pragma unroll
        for (int c = 0; c < NCHUNK; c++) { d_hiBase[n * NCHUNK + c] = acc; acc += hiCnt[c]; }
        uint32_t tb = acc;
        #pragma unroll
        for (int c = 0; c < NCHUNK; c++) { d_tBase[n * NCHUNK + c] = tb; tb += tCnt[c]; }
        d_thresh[n] = T;
    }
}

// compact + decode into exact TOPK deterministic slots.
// key = skey<<32 | (P-1-p)<<15 | slot  (order = score desc, p asc)
__global__ __launch_bounds__(512) void k_compact(const float* __restrict__ obj,
                                                 const float* __restrict__ anchors,
                                                 const float* __restrict__ reg) {
    __shared__ unsigned whi[16], wtq[16], bhi[16], btq[16];
    int n = blockIdx.y, bx = blockIdx.x;
    int T = d_thresh[n];
    const float* base = obj + (size_t)n * P + (size_t)bx * CH;
    int m0 = bx * CH;
    const int iters = (CH + 511) / 512;   // 19
    int lane = threadIdx.x & 31, warp = threadIdx.x >> 5;

    int chi = 0, ctq = 0;
    for (int it = 0; it < iters; it++) {
        int i = it * 512 + threadIdx.x;
        if (i < CH) {
            int b = (int)(lkey(base[i]) >> SHIFT);
            chi += (b > T);
            ctq += (b == T);
        }
    }
    unsigned shi = __reduce_add_sync(0xFFFFFFFFu, (unsigned)chi);
    unsigned stq = __reduce_add_sync(0xFFFFFFFFu, (unsigned)ctq);
    if (lane == 0) { whi[warp] = shi; wtq[warp] = stq; }
    __syncthreads();
    if (threadIdx.x == 0) {
        unsigned h = d_hiBase[n * NCHUNK + bx];
        unsigned tb = d_tBase[n * NCHUNK + bx];
        #pragma unroll
        for (int w = 0; w < 16; w++) { bhi[w] = h; h += whi[w]; btq[w] = tb; tb += wtq[w]; }
    }
    __syncthreads();

    unsigned hibase = bhi[warp], tqbase = btq[warp];
    u64*    ckeys = d_ckeys + (size_t)n * TOPK;
    float4* cbox  = d_cbox  + (size_t)n * TOPK;
    for (int it = 0; it < iters; it++) {
        int i = it * 512 + threadIdx.x;
        bool hi = false, tq = false;
        float v = 0.0f;
        if (i < CH) {
            v = base[i];
            int b = (int)(lkey(v) >> SHIFT);
            hi = (b > T);
            tq = (b == T);
        }
        unsigned mhi = __ballot_sync(0xFFFFFFFFu, hi);
        unsigned mtq = __ballot_sync(0xFFFFFFFFu, tq);
        unsigned slot = 0;
        bool wr = false;
        if (hi) { slot = hibase + __popc(mhi & ((1u << lane) - 1)); wr = true; }
        else if (tq) {
            slot = tqbase + __popc(mtq & ((1u << lane) - 1));
            wr = slot < (unsigned)TOPK;
        }
        hibase += __popc(mhi);
        tqbase += __popc(mtq);
        if (wr) {
            int m = m0 + i;
            int a = m / HW;
            int rem = m - a * HW;            // y*W + x
            int p = rem * A + a;
            ckeys[slot] = ((u64)skey(v) << 32) | ((u64)(uint32_t)(P - 1 - p) << 15)
                        | (u64)slot;
            const float4 anc = *(const float4*)(anchors + ((size_t)n * P + p) * 4);
            float aw = anc.z - anc.x + 1.0f, ah = anc.w - anc.y + 1.0f;
            float acx = anc.x + 0.5f * aw,  acy = anc.y + 0.5f * ah;
            size_t rb = (size_t)((n * A + a) * 4) * HW + (size_t)rem;
            float dx = __ldg(reg + rb);
            float dy = __ldg(reg + rb + HW);
            float dw = fminf(__ldg(reg + rb + 2 * (size_t)HW), XCLIP);
            float dh = fminf(__ldg(reg + rb + 3 * (size_t)HW), XCLIP);
            float pcx = dx * aw + acx, pcy = dy * ah + acy;
            float pw = expf(dw) * aw,  ph = expf(dh) * ah;
            float x1 = pcx - 0.5f * pw, y1 = pcy - 0.5f * ph;
            float x2 = pcx + 0.5f * pw - 1.0f, y2 = pcy + 0.5f * ph - 1.0f;
            x1 = fminf(fmaxf(x1, 0.0f), IMGMX);
            y1 = fminf(fmaxf(y1, 0.0f), IMGMX);
            x2 = fminf(fmaxf(x2, 0.0f), IMGMX);
            y2 = fminf(fmaxf(y2, 0.0f), IMGMX);
            cbox[slot] = make_float4(x1, y1, x2, y2);
        }
    }
}

// ----------------------------------------------------------------------------
#define CSWAP(x, y, d) { if (((x) < (y)) == (d)) { u64 _t = (x); (x) = (y); (y) = _t; } }
#define IOU_GT(px1, py1, px2, py2, pa, qx1, qy1, qx2, qy2, qa, res) {          \
    float _iw = fminf(px2, qx2) - fmaxf(px1, qx1) + 1.0f;                      \
    float _ih = fminf(py2, qy2) - fmaxf(py1, qy1) + 1.0f;                      \
    _iw = fmaxf(_iw, 0.0f); _ih = fmaxf(_ih, 0.0f);                            \
    float _in = _iw * _ih;                                                     \
    res = _in > 0.5f * ((pa) + (qa) - _in);                                    \
}

__device__ __forceinline__ void shfl_pass(u64* r, unsigned jl, bool d, unsigned tid) {
    bool upper = (tid & jl) != 0;
    bool keepMax = (d != upper);
    #pragma unroll
    for (int e = 0; e < 4; e++) {
        u64 v = __shfl_xor_sync(0xFFFFFFFFu, r[e], jl);
        r[e] = keepMax ? (r[e] > v ? r[e] : v) : (r[e] < v ? r[e] : v);
    }
}

// mega: shfl-bitonic sort of 4096 keys -> chunked greedy NMS -> output+labels
__global__ __launch_bounds__(1024, 1) void k_mega(const float* __restrict__ cls,
                                                  float* __restrict__ out) {
    extern __shared__ char raw[];
    u64*   s    = (u64*)raw;                 // 4096*8
    float* sx1  = (float*)(s + TOPK);        // 4096*4 each
    float* sy1  = sx1 + TOPK;
    float* sx2  = sy1 + TOPK;
    float* sy2  = sx2 + TOPK;
    float* sar  = sy2 + TOPK;
    float* kx1  = sar + TOPK;                // kept list, 304 each
    float* ky1  = kx1 + 304;
    float* kx2  = ky1 + 304;
    float* ky2  = kx2 + 304;
    float* kar  = ky2 + 304;
    float* ksc  = kar + 304;
    int*   kp   = (int*)(ksc + 304);
    int*   ssup = kp + 304;                  // 32
    unsigned* smat = (unsigned*)(ssup + 32); // 32 pair-matrix rows
    __shared__ int snkept;

    const int n = blockIdx.x;
    const int tid = threadIdx.x;
    const int lane = tid & 31, warp = tid >> 5;

    // ---- load keys + boxes ----
    for (int i = tid; i < TOPK; i += 1024) {
        s[i] = d_ckeys[(size_t)n * TOPK + i];
        float4 b = d_cbox[(size_t)n * TOPK + i];
        sx1[i] = b.x; sy1[i] = b.y; sx2[i] = b.z; sy2[i] = b.w;
        sar[i] = (b.z - b.x + 1.0f) * (b.w - b.y + 1.0f);
    }
    if (tid == 0) snkept = 0;
    __syncthreads();

    // ---- bitonic sort (descending), 4 elems/thread, shfl for j<=64 ----
    const unsigned g0 = tid * 4u;
    u64 r[4];
    {
        #pragma unroll
        for (int e = 0; e < 4; e++) r[e] = s[g0 + e];
        CSWAP(r[0], r[1], true);  CSWAP(r[2], r[3], false);
        {
            bool d = ((g0 & 4u) == 0u);
            CSWAP(r[0], r[2], d); CSWAP(r[1], r[3], d);
            CSWAP(r[0], r[1], d); CSWAP(r[2], r[3], d);
        }
        #pragma unroll
        for (unsigned k = 8; k <= 128; k <<= 1) {
            bool d = ((g0 & k) == 0u);
            for (unsigned j = k >> 1; j >= 4; j >>= 1)
                shfl_pass(r, j >> 2, d, tid);
            CSWAP(r[0], r[2], d); CSWAP(r[1], r[3], d);
            CSWAP(r[0], r[1], d); CSWAP(r[2], r[3], d);
        }
        #pragma unroll
        for (int e = 0; e < 4; e++) s[g0 + e] = r[e];
    }
    __syncthreads();

    for (unsigned k = 256; k <= (unsigned)TOPK; k <<= 1) {
        for (unsigned j = k >> 1; j >= 128; j >>= 1) {
            for (unsigned q = tid; q < TOPK / 2; q += 1024) {
                unsigned low = q & (j - 1);
                unsigned i = ((q ^ low) << 1) | low;
                unsigned ix = i | j;
                u64 a = s[i], b = s[ix];
                bool desc = ((i & k) == 0);
                if ((a < b) == desc) { s[i] = b; s[ix] = a; }
            }
            __syncthreads();
        }
        {
            #pragma unroll
            for (int e = 0; e < 4; e++) r[e] = s[g0 + e];
            bool d = ((g0 & k) == 0u);
            for (unsigned j = 64; j >= 4; j >>= 1)
                shfl_pass(r, j >> 2, d, tid);
            CSWAP(r[0], r[2], d); CSWAP(r[1], r[3], d);
            CSWAP(r[0], r[1], d); CSWAP(r[2], r[3], d);
            #pragma unroll
            for (int e = 0; e < 4; e++) s[g0 + e] = r[e];
        }
        __syncthreads();
    }

    // ---- chunked greedy NMS ----
    for (int c = 0; c < TOPK / 32; c++) {
        int nk = snkept;
        if (nk >= KEEP) break;

        // phase 1: warp w: (a) test box w vs kept list; (b) pair-matrix row w
        {
            unsigned slotw = (unsigned)s[c * 32 + warp] & 0xFFFu;
            float bx1 = sx1[slotw], by1 = sy1[slotw];
            float bx2 = sx2[slotw], by2 = sy2[slotw], ba = sar[slotw];
            bool sup = false;
            for (int t = lane; t < nk; t += 32) {
                bool o;
                IOU_GT(bx1, by1, bx2, by2, ba, kx1[t], ky1[t], kx2[t], ky2[t], kar[t], o);
                sup |= o;
            }
            unsigned any = __ballot_sync(0xFFFFFFFFu, sup);
            // intra-chunk: box w vs box lane
            unsigned slotl = (unsigned)s[c * 32 + lane] & 0xFFFu;
            bool o2;
            IOU_GT(bx1, by1, bx2, by2, ba,
                   sx1[slotl], sy1[slotl], sx2[slotl], sy2[slotl], sar[slotl], o2);
            unsigned row = __ballot_sync(0xFFFFFFFFu, o2);
            if (lane == 0) { ssup[warp] = (any != 0); smat[warp] = row; }
        }
        __syncthreads();

        // phase 2: warp 0 bitmask scan + kept writes
        if (warp == 0) {
            u64 key = s[c * 32 + lane];
            unsigned slot = (unsigned)key & 0xFFFu;
            unsigned myrow = smat[lane];
            unsigned alive = ~__ballot_sync(0xFFFFFFFFu, ssup[lane] != 0);
            unsigned picks = 0;
            int navail = KEEP - nk;
            int np = 0;
            while (alive && np < navail) {
                int kk = __ffs(alive) - 1;
                picks |= 1u << kk;
                np++;
                unsigned rk = __shfl_sync(0xFFFFFFFFu, myrow, kk);
                alive &= ~rk;
                alive &= ~(1u << kk);
            }
            if ((picks >> lane) & 1u) {
                int pos = nk + __popc(picks & ((1u << lane) - 1u));
                kx1[pos] = sx1[slot]; ky1[pos] = sy1[slot];
                kx2[pos] = sx2[slot]; ky2[pos] = sy2[slot];
                kar[pos] = sar[slot];
                ksc[pos] = __uint_as_float((uint32_t)(key >> 32) & 0x7FFFFFFFu);
                kp[pos]  = P - 1 - (int)(((uint32_t)key >> 15) & 0x1FFFFu);
            }
            if (lane == 0) snkept = nk + np;
        }
        __syncthreads();
    }

    // ---- output boxes/scores ----
    int kept = snkept;
    for (int k = tid; k < KEEP; k += 1024) {
        float* o = out + (size_t)(n * KEEP + k) * 6;
        if (k < kept) {
            o[0] = kx1[k]; o[1] = ky1[k]; o[2] = kx2[k]; o[3] = ky2[k];
            o[4] = ksc[k];
        } else {
            o[0] = 0.0f; o[1] = 0.0f; o[2] = 0.0f;
            o[3] = 0.0f; o[4] = 0.0f; o[5] = 0.0f;
        }
    }

    // ---- labels: warp per kept row, argmax over 80 classes ----
    for (int rI = warp; rI < kept; rI += 32) {
        int p = kp[rI];
        int a = p % A;
        int hw = p / A;
        size_t base = (size_t)((n * A + a) * C) * HW + (size_t)hw;
        float best = -INFINITY;
        int bc = 0;
        for (int cc = lane; cc < C; cc += 32) {
            float v = __ldg(cls + base + (size_t)cc * HW);
            if (v > best) { best = v; bc = cc; }
        }
        #pragma unroll
        for (int off = 16; off; off >>= 1) {
            float ov = __shfl_xor_sync(0xFFFFFFFFu, best, off);
            int   oc = __shfl_xor_sync(0xFFFFFFFFu, bc, off);
            if (ov > best || (ov == best && oc < bc)) { best = ov; bc = oc; }
        }
        if (lane == 0) out[(size_t)(n * KEEP + rI) * 6 + 5] = (float)(bc + 1);
    }
}

}  // namespace yolo

// ============================================================================
extern "C" void kernel_launch(void* const* d_in, const int* in_sizes, int n_in,
                              void* d_out, int out_size) {
    using namespace yolo;
    const float* anchors = (const float*)d_in[0];   // [16, 76800, 4]
    const float* obj     = (const float*)d_in[1];   // [16, 3, 160, 160]
    const float* reg     = (const float*)d_in[2];   // [16, 12, 160, 160]
    const float* cls     = (const float*)d_in[3];   // [16, 240, 160, 160]
    float* out = (float*)d_out;                     // [16, 300, 6]

    const int MEGA_SMEM = TOPK * (int)sizeof(u64)       // 32768
                        + TOPK * 5 * (int)sizeof(float) // 81920
                        + 304 * 7 * 4 + 64 * 4;         // 8768  => 123456

    cudaFuncSetAttribute(k_mega, cudaFuncAttributeMaxDynamicSharedMemorySize,
                         MEGA_SMEM);

    k_hist<<<dim3(NCHUNK, NBATCH), 512>>>(obj);
    k_thresh<<<NBATCH, 256>>>();
    k_compact<<<dim3(NCHUNK, NBATCH), 512>>>(obj, anchors, reg);
    k_mega<<<NBATCH, 1024, MEGA_SMEM>>>(cls, out);
}

// round 8
// speedup vs baseline: 3.9570x; 1.0241x over previous
#include <cuda_runtime.h>
#include <cstdint>
#include <math.h>

// ============================================================================
// YOLOv3 post-processor: sigmoid -> top-4096 -> decode/clip -> greedy NMS(300)
// -> [16, 300, 6] (box4 | score | label)
// 3 kernels: hist, compact(thresh+decode), mega(sort+NMS+labels)
// ============================================================================

namespace yolo {

constexpr int NBATCH = 16, A = 3, H = 160, W = 160, C = 80;
constexpr int P = A * H * W;       // 76800
constexpr int HW = H * W;          // 25600
constexpr int TOPK = 4096;
constexpr int KEEP = 300;
constexpr int NBINS = 2048;        // top 11 bits of logit order-key
constexpr int SHIFT = 21;          // 32 - 11
constexpr int NCHUNK = 8;
constexpr int CH = P / NCHUNK;     // 9600
constexpr float XCLIP = 4.135166556742356f;   // log(1000/16)
constexpr float IMGMX = 639.0f;               // 640 - TO_REMOVE

typedef unsigned long long u64;

// ---- scratch ----
__device__ uint32_t d_histB[NBATCH * NCHUNK * NBINS];
__device__ u64      d_ckeys[NBATCH * TOPK];
__device__ float4   d_cbox[NBATCH * TOPK];

// order-preserving uint key of a float
__device__ __forceinline__ uint32_t lkey(float v) {
    uint32_t u = __float_as_uint(v);
    return u ^ (uint32_t)(((int)u >> 31) | 0x80000000);
}
// exact sigmoid key (sigmoid >= 0 -> set sign bit); candidates only
__device__ __forceinline__ uint32_t skey(float logit) {
    float s = 1.0f / (1.0f + expf(-logit));
    return __float_as_uint(s) | 0x80000000u;
}

// ----------------------------------------------------------------------------
__global__ void k_hist(const float* __restrict__ obj) {
    __shared__ uint32_t sh[NBINS];
    int n = blockIdx.y, bx = blockIdx.x;
    for (int i = threadIdx.x; i < NBINS; i += blockDim.x) sh[i] = 0;
    __syncthreads();
    const float4* base = (const float4*)(obj + (size_t)n * P + (size_t)bx * CH);
    for (int i = threadIdx.x; i < CH / 4; i += blockDim.x) {
        float4 v = base[i];
        atomicAdd(&sh[lkey(v.x) >> SHIFT], 1u);
        atomicAdd(&sh[lkey(v.y) >> SHIFT], 1u);
        atomicAdd(&sh[lkey(v.z) >> SHIFT], 1u);
        atomicAdd(&sh[lkey(v.w) >> SHIFT], 1u);
    }
    __syncthreads();
    uint32_t* hb = d_histB + (size_t)(n * NCHUNK + bx) * NBINS;
    for (int i = threadIdx.x; i < NBINS; i += blockDim.x) hb[i] = sh[i];
}

// fused threshold + compact + decode into exact TOPK deterministic slots.
// key = skey<<32 | (P-1-p)<<15 | slot  (order = score desc, p asc)
__global__ __launch_bounds__(512) void k_compact(const float* __restrict__ obj,
                                                 const float* __restrict__ anchors,
                                                 const float* __restrict__ reg) {
    __shared__ uint32_t sh[NBINS];
    __shared__ uint32_t part[64];
    __shared__ uint32_t hiCnt[NCHUNK], tCnt[NCHUNK];
    __shared__ int sT;
    __shared__ unsigned sHiBase, sTBase;
    __shared__ unsigned whi[16], wtq[16], bhi[16], btq[16];

    int n = blockIdx.y, bx = blockIdx.x;
    int t = threadIdx.x;
    int lane = t & 31, warp = t >> 5;
    const uint32_t* hb = d_histB + (size_t)n * NCHUNK * NBINS;

    // --- derive threshold T (redundant per block; histB is L2-hot) ---
    for (int i = t; i < NBINS; i += 512) {
        uint32_t s = 0;
        #pragma unroll
        for (int b = 0; b < NCHUNK; b++) s += hb[(size_t)b * NBINS + i];
        sh[i] = s;
    }
    __syncthreads();
    if (t < 64) {
        uint32_t s = 0;
        for (int b = t * 32; b < t * 32 + 32; b++) s += sh[b];
        part[t] = s;
    }
    __syncthreads();
    if (t == 0) {
        uint32_t acc = 0;
        int seg = 0;
        for (int pt = 63; pt >= 0; pt--) {
            if (acc + part[pt] >= (uint32_t)TOPK) { seg = pt; break; }
            acc += part[pt];
        }
        int T = seg * 32;
        for (int b = seg * 32 + 31; b >= seg * 32; b--) {
            acc += sh[b];
            if (acc >= (uint32_t)TOPK) { T = b; break; }
        }
        sT = T;
    }
    __syncthreads();
    int T = sT;
    if (warp < NCHUNK) {
        uint32_t s = 0;
        for (int b = T + 1 + lane; b < NBINS; b += 32)
            s += hb[(size_t)warp * NBINS + b];
        s = __reduce_add_sync(0xFFFFFFFFu, s);
        if (lane == 0) {
            hiCnt[warp] = s;
            tCnt[warp] = hb[(size_t)warp * NBINS + T];
        }
    }
    __syncthreads();
    if (t == 0) {
        unsigned acc = 0, myHi = 0;
        #pragma unroll
        for (int c = 0; c < NCHUNK; c++) { if (c == bx) myHi = acc; acc += hiCnt[c]; }
        unsigned tb = acc, myT = 0;
        #pragma unroll
        for (int c = 0; c < NCHUNK; c++) { if (c == bx) myT = tb; tb += tCnt[c]; }
        sHiBase = myHi;
        sTBase = myT;
    }
    __syncthreads();

    // --- pass 1: per-warp counts over this chunk ---
    const float* base = obj + (size_t)n * P + (size_t)bx * CH;
    int m0 = bx * CH;
    const int iters = (CH + 511) / 512;   // 19
    int chi = 0, ctq = 0;
    for (int it = 0; it < iters; it++) {
        int i = it * 512 + t;
        if (i < CH) {
            int b = (int)(lkey(base[i]) >> SHIFT);
            chi += (b > T);
            ctq += (b == T);
        }
    }
    unsigned shiW = __reduce_add_sync(0xFFFFFFFFu, (unsigned)chi);
    unsigned stqW = __reduce_add_sync(0xFFFFFFFFu, (unsigned)ctq);
    if (lane == 0) { whi[warp] = shiW; wtq[warp] = stqW; }
    __syncthreads();
    if (t == 0) {
        unsigned h = sHiBase, tb = sTBase;
        #pragma unroll
        for (int w = 0; w < 16; w++) { bhi[w] = h; h += whi[w]; btq[w] = tb; tb += wtq[w]; }
    }
    __syncthreads();

    // --- pass 2: deterministic placement + decode ---
    unsigned hibase = bhi[warp], tqbase = btq[warp];
    u64*    ckeys = d_ckeys + (size_t)n * TOPK;
    float4* cbox  = d_cbox  + (size_t)n * TOPK;
    for (int it = 0; it < iters; it++) {
        int i = it * 512 + t;
        bool hi = false, tq = false;
        float v = 0.0f;
        if (i < CH) {
            v = base[i];
            int b = (int)(lkey(v) >> SHIFT);
            hi = (b > T);
            tq = (b == T);
        }
        unsigned mhi = __ballot_sync(0xFFFFFFFFu, hi);
        unsigned mtq = __ballot_sync(0xFFFFFFFFu, tq);
        unsigned slot = 0;
        bool wr = false;
        if (hi) { slot = hibase + __popc(mhi & ((1u << lane) - 1)); wr = true; }
        else if (tq) {
            slot = tqbase + __popc(mtq & ((1u << lane) - 1));
            wr = slot < (unsigned)TOPK;
        }
        hibase += __popc(mhi);
        tqbase += __popc(mtq);
        if (wr) {
            int m = m0 + i;
            int a = m / HW;
            int rem = m - a * HW;            // y*W + x
            int p = rem * A + a;
            ckeys[slot] = ((u64)skey(v) << 32) | ((u64)(uint32_t)(P - 1 - p) << 15)
                        | (u64)slot;
            const float4 anc = *(const float4*)(anchors + ((size_t)n * P + p) * 4);
            float aw = anc.z - anc.x + 1.0f, ah = anc.w - anc.y + 1.0f;
            float acx = anc.x + 0.5f * aw,  acy = anc.y + 0.5f * ah;
            size_t rb = (size_t)((n * A + a) * 4) * HW + (size_t)rem;
            float dx = __ldg(reg + rb);
            float dy = __ldg(reg + rb + HW);
            float dw = fminf(__ldg(reg + rb + 2 * (size_t)HW), XCLIP);
            float dh = fminf(__ldg(reg + rb + 3 * (size_t)HW), XCLIP);
            float pcx = dx * aw + acx, pcy = dy * ah + acy;
            float pw = expf(dw) * aw,  ph = expf(dh) * ah;
            float x1 = pcx - 0.5f * pw, y1 = pcy - 0.5f * ph;
            float x2 = pcx + 0.5f * pw - 1.0f, y2 = pcy + 0.5f * ph - 1.0f;
            x1 = fminf(fmaxf(x1, 0.0f), IMGMX);
            y1 = fminf(fmaxf(y1, 0.0f), IMGMX);
            x2 = fminf(fmaxf(x2, 0.0f), IMGMX);
            y2 = fminf(fmaxf(y2, 0.0f), IMGMX);
            cbox[slot] = make_float4(x1, y1, x2, y2);
        }
    }
}

// ----------------------------------------------------------------------------
#define CSWAP(x, y, d) { if (((x) < (y)) == (d)) { u64 _t = (x); (x) = (y); (y) = _t; } }
#define IOU_GT(px1, py1, px2, py2, pa, qx1, qy1, qx2, qy2, qa, res) {          \
    float _iw = fminf(px2, qx2) - fmaxf(px1, qx1) + 1.0f;                      \
    float _ih = fminf(py2, qy2) - fmaxf(py1, qy1) + 1.0f;                      \
    _iw = fmaxf(_iw, 0.0f); _ih = fmaxf(_ih, 0.0f);                            \
    float _in = _iw * _ih;                                                     \
    res = _in > 0.5f * ((pa) + (qa) - _in);                                    \
}

__device__ __forceinline__ void shfl_pass(u64* r, unsigned jl, bool d, unsigned tid) {
    bool upper = (tid & jl) != 0;
    bool keepMax = (d != upper);
    #pragma unroll
    for (int e = 0; e < 4; e++) {
        u64 v = __shfl_xor_sync(0xFFFFFFFFu, r[e], jl);
        r[e] = keepMax ? (r[e] > v ? r[e] : v) : (r[e] < v ? r[e] : v);
    }
}

// mega: shfl-bitonic sort of 4096 -> 64-chunk greedy NMS -> output + labels
__global__ __launch_bounds__(1024, 1) void k_mega(const float* __restrict__ cls,
                                                  float* __restrict__ out) {
    extern __shared__ char raw[];
    u64*   s    = (u64*)raw;                 // 4096*8
    float* sx1  = (float*)(s + TOPK);        // 4096*4 each
    float* sy1  = sx1 + TOPK;
    float* sx2  = sy1 + TOPK;
    float* sy2  = sx2 + TOPK;
    float* sar  = sy2 + TOPK;
    float* kx1  = sar + TOPK;                // kept list, 304 each
    float* ky1  = kx1 + 304;
    float* kx2  = ky1 + 304;
    float* ky2  = kx2 + 304;
    float* kar  = ky2 + 304;
    float* ksc  = kar + 304;
    int*   kp   = (int*)(ksc + 304);
    int*   ssup = kp + 304;                  // 64 (2128 ints so far -> 8-aligned next)
    u64*   smat = (u64*)(ssup + 64);         // 64 pair-matrix rows
    __shared__ int snkept;

    const int n = blockIdx.x;
    const int tid = threadIdx.x;
    const int lane = tid & 31, warp = tid >> 5;

    // ---- load keys + boxes ----
    for (int i = tid; i < TOPK; i += 1024) {
        s[i] = d_ckeys[(size_t)n * TOPK + i];
        float4 b = d_cbox[(size_t)n * TOPK + i];
        sx1[i] = b.x; sy1[i] = b.y; sx2[i] = b.z; sy2[i] = b.w;
        sar[i] = (b.z - b.x + 1.0f) * (b.w - b.y + 1.0f);
    }
    if (tid == 0) snkept = 0;
    __syncthreads();

    // ---- bitonic sort (descending), 4 elems/thread, shfl for j<=64 ----
    const unsigned g0 = tid * 4u;
    u64 r[4];
    {
        #pragma unroll
        for (int e = 0; e < 4; e++) r[e] = s[g0 + e];
        CSWAP(r[0], r[1], true);  CSWAP(r[2], r[3], false);
        {
            bool d = ((g0 & 4u) == 0u);
            CSWAP(r[0], r[2], d); CSWAP(r[1], r[3], d);
            CSWAP(r[0], r[1], d); CSWAP(r[2], r[3], d);
        }
        #pragma unroll
        for (unsigned k = 8; k <= 128; k <<= 1) {
            bool d = ((g0 & k) == 0u);
            for (unsigned j = k >> 1; j >= 4; j >>= 1)
                shfl_pass(r, j >> 2, d, tid);
            CSWAP(r[0], r[2], d); CSWAP(r[1], r[3], d);
            CSWAP(r[0], r[1], d); CSWAP(r[2], r[3], d);
        }
        #pragma unroll
        for (int e = 0; e < 4; e++) s[g0 + e] = r[e];
    }
    __syncthreads();

    for (unsigned k = 256; k <= (unsigned)TOPK; k <<= 1) {
        for (unsigned j = k >> 1; j >= 128; j >>= 1) {
            for (unsigned q = tid; q < TOPK / 2; q += 1024) {
                unsigned low = q & (j - 1);
                unsigned i = ((q ^ low) << 1) | low;
                unsigned ix = i | j;
                u64 a = s[i], b = s[ix];
                bool desc = ((i & k) == 0);
                if ((a < b) == desc) { s[i] = b; s[ix] = a; }
            }
            __syncthreads();
        }
        {
            #pragma unroll
            for (int e = 0; e < 4; e++) r[e] = s[g0 + e];
            bool d = ((g0 & k) == 0u);
            for (unsigned j = 64; j >= 4; j >>= 1)
                shfl_pass(r, j >> 2, d, tid);
            CSWAP(r[0], r[2], d); CSWAP(r[1], r[3], d);
            CSWAP(r[0], r[1], d); CSWAP(r[2], r[3], d);
            #pragma unroll
            for (int e = 0; e < 4; e++) s[g0 + e] = r[e];
        }
        __syncthreads();
    }

    // ---- 64-wide chunked greedy NMS ----
    for (int c = 0; c < TOPK / 64; c++) {
        int nk = snkept;
        if (nk >= KEEP) break;

        // phase 1: warp w owns boxes lo=64c+w, hi=64c+w+32
        {
            unsigned slotLo = (unsigned)s[c * 64 + warp] & 0xFFFu;
            unsigned slotHi = (unsigned)s[c * 64 + warp + 32] & 0xFFFu;
            float lx1 = sx1[slotLo], ly1 = sy1[slotLo];
            float lx2 = sx2[slotLo], ly2 = sy2[slotLo], la = sar[slotLo];
            float hx1 = sx1[slotHi], hy1 = sy1[slotHi];
            float hx2 = sx2[slotHi], hy2 = sy2[slotHi], ha = sar[slotHi];

            bool supLo = false, supHi = false;
            for (int tt = lane; tt < nk; tt += 32) {
                float qx1 = kx1[tt], qy1 = ky1[tt];
                float qx2 = kx2[tt], qy2 = ky2[tt], qa = kar[tt];
                bool o1, o2;
                IOU_GT(lx1, ly1, lx2, ly2, la, qx1, qy1, qx2, qy2, qa, o1);
                IOU_GT(hx1, hy1, hx2, hy2, ha, qx1, qy1, qx2, qy2, qa, o2);
                supLo |= o1;
                supHi |= o2;
            }
            unsigned anyLo = __ballot_sync(0xFFFFFFFFu, supLo);
            unsigned anyHi = __ballot_sync(0xFFFFFFFFu, supHi);

            // intra-chunk matrix: lane-lo / lane-hi boxes
            unsigned sl = (unsigned)s[c * 64 + lane] & 0xFFFu;
            unsigned sh2 = (unsigned)s[c * 64 + 32 + lane] & 0xFFFu;
            float ax1 = sx1[sl], ay1 = sy1[sl], ax2 = sx2[sl], ay2 = sy2[sl], aa = sar[sl];
            float bx1 = sx1[sh2], by1 = sy1[sh2], bx2 = sx2[sh2], by2 = sy2[sh2], ba = sar[sh2];
            bool o;
            IOU_GT(lx1, ly1, lx2, ly2, la, ax1, ay1, ax2, ay2, aa, o);
            unsigned rLL = __ballot_sync(0xFFFFFFFFu, o);
            IOU_GT(lx1, ly1, lx2, ly2, la, bx1, by1, bx2, by2, ba, o);
            unsigned rLH = __ballot_sync(0xFFFFFFFFu, o);
            IOU_GT(hx1, hy1, hx2, hy2, ha, ax1, ay1, ax2, ay2, aa, o);
            unsigned rHL = __ballot_sync(0xFFFFFFFFu, o);
            IOU_GT(hx1, hy1, hx2, hy2, ha, bx1, by1, bx2, by2, ba, o);
            unsigned rHH = __ballot_sync(0xFFFFFFFFu, o);

            if (lane == 0) {
                ssup[warp]      = (anyLo != 0);
                ssup[warp + 32] = (anyHi != 0);
                smat[warp]      = (u64)rLL | ((u64)rLH << 32);
                smat[warp + 32] = (u64)rHL | ((u64)rHH << 32);
            }
        }
        __syncthreads();

        // phase 2: warp 0 64-bit bitmask scan + kept writes
        if (warp == 0) {
            unsigned aLo = ~__ballot_sync(0xFFFFFFFFu, ssup[lane] != 0);
            unsigned aHi = ~__ballot_sync(0xFFFFFFFFu, ssup[lane + 32] != 0);
            u64 alive = (u64)aLo | ((u64)aHi << 32);
            u64 picks = 0;
            int navail = KEEP - nk;
            int np = 0;
            while (alive && np < navail) {
                int kk = __ffsll((long long)alive) - 1;
                picks |= 1ull << kk;
                np++;
                u64 row = smat[kk];
                alive &= ~row;
                alive &= ~(1ull << kk);
            }
            #pragma unroll
            for (int h = 0; h < 2; h++) {
                int idx = lane + 32 * h;
                if ((picks >> idx) & 1ull) {
                    int pos = nk + (int)__popcll(picks & ((1ull << idx) - 1ull));
                    u64 key = s[c * 64 + idx];
                    unsigned slot = (unsigned)key & 0xFFFu;
                    kx1[pos] = sx1[slot]; ky1[pos] = sy1[slot];
                    kx2[pos] = sx2[slot]; ky2[pos] = sy2[slot];
                    kar[pos] = sar[slot];
                    ksc[pos] = __uint_as_float((uint32_t)(key >> 32) & 0x7FFFFFFFu);
                    kp[pos]  = P - 1 - (int)(((uint32_t)key >> 15) & 0x1FFFFu);
                }
            }
            if (lane == 0) snkept = nk + np;
        }
        __syncthreads();
    }

    // ---- output boxes/scores ----
    int kept = snkept;
    for (int k = tid; k < KEEP; k += 1024) {
        float* o = out + (size_t)(n * KEEP + k) * 6;
        if (k < kept) {
            o[0] = kx1[k]; o[1] = ky1[k]; o[2] = kx2[k]; o[3] = ky2[k];
            o[4] = ksc[k];
        } else {
            o[0] = 0.0f; o[1] = 0.0f; o[2] = 0.0f;
            o[3] = 0.0f; o[4] = 0.0f; o[5] = 0.0f;
        }
    }

    // ---- labels: 3 rows per warp batched for MLP, argmax over 80 classes ----
    for (int r0 = warp; r0 < kept; r0 += 96) {
        float vals[3][3];
        bool valid[3];
        #pragma unroll
        for (int g = 0; g < 3; g++) {
            int rI = r0 + 32 * g;
            bool v = rI < kept;
            valid[g] = v;
            int p = v ? kp[rI] : 0;
            int a = p % A;
            int hw = p / A;
            const float* bp = cls + (size_t)((n * A + a) * C) * HW + (size_t)hw;
            #pragma unroll
            for (int cc = 0; cc < 3; cc++) {
                int cidx = lane + 32 * cc;
                vals[g][cc] = (v && cidx < C) ? __ldg(bp + (size_t)cidx * HW)
                                              : -INFINITY;
            }
        }
        #pragma unroll
        for (int g = 0; g < 3; g++) {
            if (!valid[g]) break;
            float best = -INFINITY;
            int bc = 0;
            #pragma unroll
            for (int cc = 0; cc < 3; cc++) {
                int cidx = lane + 32 * cc;
                if (vals[g][cc] > best) { best = vals[g][cc]; bc = cidx; }
            }
            #pragma unroll
            for (int off = 16; off; off >>= 1) {
                float ov = __shfl_xor_sync(0xFFFFFFFFu, best, off);
                int   oc = __shfl_xor_sync(0xFFFFFFFFu, bc, off);
                if (ov > best || (ov == best && oc < bc)) { best = ov; bc = oc; }
            }
            if (lane == 0)
                out[(size_t)(n * KEEP + r0 + 32 * g) * 6 + 5] = (float)(bc + 1);
        }
    }
}

}  // namespace yolo

// ============================================================================
extern "C" void kernel_launch(void* const* d_in, const int* in_sizes, int n_in,
                              void* d_out, int out_size) {
    using namespace yolo;
    const float* anchors = (const float*)d_in[0];   // [16, 76800, 4]
    const float* obj     = (const float*)d_in[1];   // [16, 3, 160, 160]
    const float* reg     = (const float*)d_in[2];   // [16, 12, 160, 160]
    const float* cls     = (const float*)d_in[3];   // [16, 240, 160, 160]
    float* out = (float*)d_out;                     // [16, 300, 6]

    const int MEGA_SMEM = TOPK * (int)sizeof(u64)       // 32768
                        + TOPK * 5 * (int)sizeof(float) // 81920
                        + 304 * 7 * 4                   // 8512
                        + 64 * 4 + 64 * 8;              // 768   => 123968

    cudaFuncSetAttribute(k_mega, cudaFuncAttributeMaxDynamicSharedMemorySize,
                         MEGA_SMEM);

    k_hist<<<dim3(NCHUNK, NBATCH), 512>>>(obj);
    k_compact<<<dim3(NCHUNK, NBATCH), 512>>>(obj, anchors, reg);
    k_mega<<<NBATCH, 1024, MEGA_SMEM>>>(cls, out);
}

// round 9
// speedup vs baseline: 4.0412x; 1.0213x over previous
#include <cuda_runtime.h>
#include <cstdint>
#include <math.h>

// ============================================================================
// YOLOv3 post-processor: sigmoid -> top-4096 -> decode/clip -> greedy NMS(300)
// -> [16, 300, 6] (box4 | score | label)
// 3 kernels: hist, compact(thresh+decode), mega(sort+NMS+labels)
// ============================================================================

namespace yolo {

constexpr int NBATCH = 16, A = 3, H = 160, W = 160, C = 80;
constexpr int P = A * H * W;       // 76800
constexpr int HW = H * W;          // 25600
constexpr int TOPK = 4096;
constexpr int KEEP = 300;
constexpr int NBINS = 2048;        // top 11 bits of logit order-key
constexpr int SHIFT = 21;          // 32 - 11
constexpr int NCHUNK = 16;
constexpr int CH = P / NCHUNK;     // 4800
constexpr float XCLIP = 4.135166556742356f;   // log(1000/16)
constexpr float IMGMX = 639.0f;               // 640 - TO_REMOVE

typedef unsigned long long u64;

// ---- scratch ----
__device__ uint32_t d_histB[NBATCH * NCHUNK * NBINS];
__device__ u64      d_ckeys[NBATCH * TOPK];
__device__ float4   d_cbox[NBATCH * TOPK];

// order-preserving uint key of a float
__device__ __forceinline__ uint32_t lkey(float v) {
    uint32_t u = __float_as_uint(v);
    return u ^ (uint32_t)(((int)u >> 31) | 0x80000000);
}
// exact sigmoid key (sigmoid >= 0 -> set sign bit); candidates only
__device__ __forceinline__ uint32_t skey(float logit) {
    float s = 1.0f / (1.0f + expf(-logit));
    return __float_as_uint(s) | 0x80000000u;
}

// ----------------------------------------------------------------------------
__global__ void k_hist(const float* __restrict__ obj) {
    __shared__ uint32_t sh[NBINS];
    int n = blockIdx.y, bx = blockIdx.x;
    for (int i = threadIdx.x; i < NBINS; i += blockDim.x) sh[i] = 0;
    __syncthreads();
    const float4* base = (const float4*)(obj + (size_t)n * P + (size_t)bx * CH);
    for (int i = threadIdx.x; i < CH / 4; i += blockDim.x) {
        float4 v = base[i];
        atomicAdd(&sh[lkey(v.x) >> SHIFT], 1u);
        atomicAdd(&sh[lkey(v.y) >> SHIFT], 1u);
        atomicAdd(&sh[lkey(v.z) >> SHIFT], 1u);
        atomicAdd(&sh[lkey(v.w) >> SHIFT], 1u);
    }
    __syncthreads();
    uint32_t* hb = d_histB + (size_t)(n * NCHUNK + bx) * NBINS;
    for (int i = threadIdx.x; i < NBINS; i += blockDim.x) hb[i] = sh[i];
}

// fused threshold + compact + decode into exact TOPK deterministic slots.
// key = skey<<32 | (P-1-p)<<15 | slot  (order = score desc, p asc)
__global__ __launch_bounds__(512) void k_compact(const float* __restrict__ obj,
                                                 const float* __restrict__ anchors,
                                                 const float* __restrict__ reg) {
    __shared__ uint32_t sh[NBINS];
    __shared__ uint32_t part[64];
    __shared__ uint32_t hiCnt[NCHUNK], tCnt[NCHUNK];
    __shared__ int sT;
    __shared__ unsigned sHiBase, sTBase;
    __shared__ unsigned whi[16], wtq[16], bhi[16], btq[16];

    int n = blockIdx.y, bx = blockIdx.x;
    int t = threadIdx.x;
    int lane = t & 31, warp = t >> 5;
    const uint32_t* hb = d_histB + (size_t)n * NCHUNK * NBINS;

    // --- derive threshold T (redundant per block; histB is L2-hot) ---
    for (int i = t; i < NBINS; i += 512) {
        uint32_t s = 0;
        #pragma unroll
        for (int b = 0; b < NCHUNK; b++) s += hb[(size_t)b * NBINS + i];
        sh[i] = s;
    }
    __syncthreads();
    if (t < 64) {
        uint32_t s = 0;
        for (int b = t * 32; b < t * 32 + 32; b++) s += sh[b];
        part[t] = s;
    }
    __syncthreads();
    if (t == 0) {
        uint32_t acc = 0;
        int seg = 0;
        for (int pt = 63; pt >= 0; pt--) {
            if (acc + part[pt] >= (uint32_t)TOPK) { seg = pt; break; }
            acc += part[pt];
        }
        int T = seg * 32;
        for (int b = seg * 32 + 31; b >= seg * 32; b--) {
            acc += sh[b];
            if (acc >= (uint32_t)TOPK) { T = b; break; }
        }
        sT = T;
    }
    __syncthreads();
    int T = sT;
    if (warp < NCHUNK) {
        uint32_t s = 0;
        for (int b = T + 1 + lane; b < NBINS; b += 32)
            s += hb[(size_t)warp * NBINS + b];
        s = __reduce_add_sync(0xFFFFFFFFu, s);
        if (lane == 0) {
            hiCnt[warp] = s;
            tCnt[warp] = hb[(size_t)warp * NBINS + T];
        }
    }
    __syncthreads();
    if (t == 0) {
        unsigned acc = 0, myHi = 0;
        #pragma unroll
        for (int c = 0; c < NCHUNK; c++) { if (c == bx) myHi = acc; acc += hiCnt[c]; }
        unsigned tb = acc, myT = 0;
        #pragma unroll
        for (int c = 0; c < NCHUNK; c++) { if (c == bx) myT = tb; tb += tCnt[c]; }
        sHiBase = myHi;
        sTBase = myT;
    }
    __syncthreads();

    // --- pass 1: per-warp counts over this chunk ---
    const float* base = obj + (size_t)n * P + (size_t)bx * CH;
    int m0 = bx * CH;
    const int iters = (CH + 511) / 512;   // 10
    int chi = 0, ctq = 0;
    for (int it = 0; it < iters; it++) {
        int i = it * 512 + t;
        if (i < CH) {
            int b = (int)(lkey(base[i]) >> SHIFT);
            chi += (b > T);
            ctq += (b == T);
        }
    }
    unsigned shiW = __reduce_add_sync(0xFFFFFFFFu, (unsigned)chi);
    unsigned stqW = __reduce_add_sync(0xFFFFFFFFu, (unsigned)ctq);
    if (lane == 0) { whi[warp] = shiW; wtq[warp] = stqW; }
    __syncthreads();
    if (t == 0) {
        unsigned h = sHiBase, tb = sTBase;
        #pragma unroll
        for (int w = 0; w < 16; w++) { bhi[w] = h; h += whi[w]; btq[w] = tb; tb += wtq[w]; }
    }
    __syncthreads();

    // --- pass 2: deterministic placement + decode ---
    unsigned hibase = bhi[warp], tqbase = btq[warp];
    u64*    ckeys = d_ckeys + (size_t)n * TOPK;
    float4* cbox  = d_cbox  + (size_t)n * TOPK;
    for (int it = 0; it < iters; it++) {
        int i = it * 512 + t;
        bool hi = false, tq = false;
        float v = 0.0f;
        if (i < CH) {
            v = base[i];
            int b = (int)(lkey(v) >> SHIFT);
            hi = (b > T);
            tq = (b == T);
        }
        unsigned mhi = __ballot_sync(0xFFFFFFFFu, hi);
        unsigned mtq = __ballot_sync(0xFFFFFFFFu, tq);
        unsigned slot = 0;
        bool wr = false;
        if (hi) { slot = hibase + __popc(mhi & ((1u << lane) - 1)); wr = true; }
        else if (tq) {
            slot = tqbase + __popc(mtq & ((1u << lane) - 1));
            wr = slot < (unsigned)TOPK;
        }
        hibase += __popc(mhi);
        tqbase += __popc(mtq);
        if (wr) {
            int m = m0 + i;
            int a = m / HW;
            int rem = m - a * HW;            // y*W + x
            int p = rem * A + a;
            ckeys[slot] = ((u64)skey(v) << 32) | ((u64)(uint32_t)(P - 1 - p) << 15)
                        | (u64)slot;
            const float4 anc = *(const float4*)(anchors + ((size_t)n * P + p) * 4);
            float aw = anc.z - anc.x + 1.0f, ah = anc.w - anc.y + 1.0f;
            float acx = anc.x + 0.5f * aw,  acy = anc.y + 0.5f * ah;
            size_t rb = (size_t)((n * A + a) * 4) * HW + (size_t)rem;
            float dx = __ldg(reg + rb);
            float dy = __ldg(reg + rb + HW);
            float dw = fminf(__ldg(reg + rb + 2 * (size_t)HW), XCLIP);
            float dh = fminf(__ldg(reg + rb + 3 * (size_t)HW), XCLIP);
            float pcx = dx * aw + acx, pcy = dy * ah + acy;
            float pw = expf(dw) * aw,  ph = expf(dh) * ah;
            float x1 = pcx - 0.5f * pw, y1 = pcy - 0.5f * ph;
            float x2 = pcx + 0.5f * pw - 1.0f, y2 = pcy + 0.5f * ph - 1.0f;
            x1 = fminf(fmaxf(x1, 0.0f), IMGMX);
            y1 = fminf(fmaxf(y1, 0.0f), IMGMX);
            x2 = fminf(fmaxf(x2, 0.0f), IMGMX);
            y2 = fminf(fmaxf(y2, 0.0f), IMGMX);
            cbox[slot] = make_float4(x1, y1, x2, y2);
        }
    }
}

// ----------------------------------------------------------------------------
#define CSWAP(x, y, d) { if (((x) < (y)) == (d)) { u64 _t = (x); (x) = (y); (y) = _t; } }
#define IOU_GT(px1, py1, px2, py2, pa, qx1, qy1, qx2, qy2, qa, res) {          \
    float _iw = fminf(px2, qx2) - fmaxf(px1, qx1) + 1.0f;                      \
    float _ih = fminf(py2, qy2) - fmaxf(py1, qy1) + 1.0f;                      \
    _iw = fmaxf(_iw, 0.0f); _ih = fmaxf(_ih, 0.0f);                            \
    float _in = _iw * _ih;                                                     \
    res = _in > 0.5f * ((pa) + (qa) - _in);                                    \
}

__device__ __forceinline__ void shfl_pass(u64* r, unsigned jl, bool d, unsigned tid) {
    bool upper = (tid & jl) != 0;
    bool keepMax = (d != upper);
    #pragma unroll
    for (int e = 0; e < 4; e++) {
        u64 v = __shfl_xor_sync(0xFFFFFFFFu, r[e], jl);
        r[e] = keepMax ? (r[e] > v ? r[e] : v) : (r[e] < v ? r[e] : v);
    }
}

// mega: shfl-bitonic sort of 4096 -> 128-chunk greedy NMS -> output + labels
__global__ __launch_bounds__(1024, 1) void k_mega(const float* __restrict__ cls,
                                                  float* __restrict__ out) {
    extern __shared__ char raw[];
    u64*   s    = (u64*)raw;                 // 4096*8
    float* sx1  = (float*)(s + TOPK);        // 4096*4 each
    float* sy1  = sx1 + TOPK;
    float* sx2  = sy1 + TOPK;
    float* sy2  = sx2 + TOPK;
    float* sar  = sy2 + TOPK;
    float* kx1  = sar + TOPK;                // kept list, 304 each
    float* ky1  = kx1 + 304;
    float* kx2  = ky1 + 304;
    float* ky2  = kx2 + 304;
    float* kar  = ky2 + 304;
    float* ksc  = kar + 304;
    int*   kp   = (int*)(ksc + 304);
    int*   ssup = kp + 304;                  // 128
    unsigned* smat = (unsigned*)(ssup + 128);// 128 rows * 4 words (uint4-aligned)
    __shared__ int snkept;

    const int n = blockIdx.x;
    const int tid = threadIdx.x;
    const int lane = tid & 31, warp = tid >> 5;

    // ---- load keys + boxes ----
    for (int i = tid; i < TOPK; i += 1024) {
        s[i] = d_ckeys[(size_t)n * TOPK + i];
        float4 b = d_cbox[(size_t)n * TOPK + i];
        sx1[i] = b.x; sy1[i] = b.y; sx2[i] = b.z; sy2[i] = b.w;
        sar[i] = (b.z - b.x + 1.0f) * (b.w - b.y + 1.0f);
    }
    if (tid == 0) snkept = 0;
    __syncthreads();

    // ---- bitonic sort (descending), 4 elems/thread, shfl for j<=64 ----
    const unsigned g0 = tid * 4u;
    u64 r[4];
    {
        #pragma unroll
        for (int e = 0; e < 4; e++) r[e] = s[g0 + e];
        CSWAP(r[0], r[1], true);  CSWAP(r[2], r[3], false);
        {
            bool d = ((g0 & 4u) == 0u);
            CSWAP(r[0], r[2], d); CSWAP(r[1], r[3], d);
            CSWAP(r[0], r[1], d); CSWAP(r[2], r[3], d);
        }
        #pragma unroll
        for (unsigned k = 8; k <= 128; k <<= 1) {
            bool d = ((g0 & k) == 0u);
            for (unsigned j = k >> 1; j >= 4; j >>= 1)
                shfl_pass(r, j >> 2, d, tid);
            CSWAP(r[0], r[2], d); CSWAP(r[1], r[3], d);
            CSWAP(r[0], r[1], d); CSWAP(r[2], r[3], d);
        }
        #pragma unroll
        for (int e = 0; e < 4; e++) s[g0 + e] = r[e];
    }
    __syncthreads();

    for (unsigned k = 256; k <= (unsigned)TOPK; k <<= 1) {
        for (unsigned j = k >> 1; j >= 128; j >>= 1) {
            for (unsigned q = tid; q < TOPK / 2; q += 1024) {
                unsigned low = q & (j - 1);
                unsigned i = ((q ^ low) << 1) | low;
                unsigned ix = i | j;
                u64 a = s[i], b = s[ix];
                bool desc = ((i & k) == 0);
                if ((a < b) == desc) { s[i] = b; s[ix] = a; }
            }
            __syncthreads();
        }
        {
            #pragma unroll
            for (int e = 0; e < 4; e++) r[e] = s[g0 + e];
            bool d = ((g0 & k) == 0u);
            for (unsigned j = 64; j >= 4; j >>= 1)
                shfl_pass(r, j >> 2, d, tid);
            CSWAP(r[0], r[2], d); CSWAP(r[1], r[3], d);
            CSWAP(r[0], r[1], d); CSWAP(r[2], r[3], d);
            #pragma unroll
            for (int e = 0; e < 4; e++) s[g0 + e] = r[e];
        }
        __syncthreads();
    }

    // ---- 128-wide chunked greedy NMS ----
    for (int c = 0; c < TOPK / 128; c++) {
        int nk = snkept;
        if (nk >= KEEP) break;
        const int cb = c * 128;

        // phase 1: warp w owns boxes cb + w + 32h (h=0..3)
        {
            float ox1[4], oy1[4], ox2[4], oy2[4], oa[4];
            #pragma unroll
            for (int h = 0; h < 4; h++) {
                unsigned slot = (unsigned)s[cb + warp + 32 * h] & 0xFFFu;
                ox1[h] = sx1[slot]; oy1[h] = sy1[slot];
                ox2[h] = sx2[slot]; oy2[h] = sy2[slot]; oa[h] = sar[slot];
            }
            bool sup[4] = {false, false, false, false};
            for (int tt = lane; tt < nk; tt += 32) {
                float qx1 = kx1[tt], qy1 = ky1[tt];
                float qx2 = kx2[tt], qy2 = ky2[tt], qa = kar[tt];
                #pragma unroll
                for (int h = 0; h < 4; h++) {
                    bool o;
                    IOU_GT(ox1[h], oy1[h], ox2[h], oy2[h], oa[h],
                           qx1, qy1, qx2, qy2, qa, o);
                    sup[h] |= o;
                }
            }
            unsigned any[4];
            #pragma unroll
            for (int h = 0; h < 4; h++) any[h] = __ballot_sync(0xFFFFFFFFu, sup[h]);
            if (lane == 0) {
                #pragma unroll
                for (int h = 0; h < 4; h++) ssup[warp + 32 * h] = (any[h] != 0);
            }
            // intra-chunk 4x4 ballot matrix
            unsigned roww[4][4];
            #pragma unroll
            for (int g = 0; g < 4; g++) {
                unsigned sl = (unsigned)s[cb + g * 32 + lane] & 0xFFFu;
                float qx1 = sx1[sl], qy1 = sy1[sl];
                float qx2 = sx2[sl], qy2 = sy2[sl], qa = sar[sl];
                #pragma unroll
                for (int h = 0; h < 4; h++) {
                    bool o;
                    IOU_GT(ox1[h], oy1[h], ox2[h], oy2[h], oa[h],
                           qx1, qy1, qx2, qy2, qa, o);
                    roww[h][g] = __ballot_sync(0xFFFFFFFFu, o);
                }
            }
            if (lane == 0) {
                #pragma unroll
                for (int h = 0; h < 4; h++)
                    *(uint4*)&smat[(warp + 32 * h) * 4] =
                        make_uint4(roww[h][0], roww[h][1], roww[h][2], roww[h][3]);
            }
        }
        __syncthreads();

        // phase 2: warp 0, redundant-uniform 128-bit scan
        if (warp == 0) {
            unsigned aw0 = ~__ballot_sync(0xFFFFFFFFu, ssup[lane] != 0);
            unsigned aw1 = ~__ballot_sync(0xFFFFFFFFu, ssup[lane + 32] != 0);
            unsigned aw2 = ~__ballot_sync(0xFFFFFFFFu, ssup[lane + 64] != 0);
            unsigned aw3 = ~__ballot_sync(0xFFFFFFFFu, ssup[lane + 96] != 0);
            unsigned aw[4] = {aw0, aw1, aw2, aw3};
            unsigned pk[4] = {0, 0, 0, 0};
            int navail = KEEP - nk;
            int np = 0;
            #pragma unroll 1
            for (int g = 0; g < 4; g++) {
                while (aw[g] && np < navail) {
                    int kk = __ffs(aw[g]) - 1;
                    pk[g] |= 1u << kk;
                    np++;
                    const uint4 row = *(const uint4*)&smat[(g * 32 + kk) * 4];
                    aw[0] &= ~row.x; aw[1] &= ~row.y;
                    aw[2] &= ~row.z; aw[3] &= ~row.w;
                }
                if (np >= navail) break;
            }
            int cum1 = __popc(pk[0]);
            int cum2 = cum1 + __popc(pk[1]);
            int cum3 = cum2 + __popc(pk[2]);
            int cum[4] = {0, cum1, cum2, cum3};
            #pragma unroll
            for (int g = 0; g < 4; g++) {
                if ((pk[g] >> lane) & 1u) {
                    int pos = nk + cum[g] + __popc(pk[g] & ((1u << lane) - 1u));
                    u64 key = s[cb + g * 32 + lane];
                    unsigned slot = (unsigned)key & 0xFFFu;
                    kx1[pos] = sx1[slot]; ky1[pos] = sy1[slot];
                    kx2[pos] = sx2[slot]; ky2[pos] = sy2[slot];
                    kar[pos] = sar[slot];
                    ksc[pos] = __uint_as_float((uint32_t)(key >> 32) & 0x7FFFFFFFu);
                    kp[pos]  = P - 1 - (int)(((uint32_t)key >> 15) & 0x1FFFFu);
                }
            }
            if (lane == 0) snkept = nk + np;
        }
        __syncthreads();
    }

    // ---- output boxes/scores ----
    int kept = snkept;
    for (int k = tid; k < KEEP; k += 1024) {
        float* o = out + (size_t)(n * KEEP + k) * 6;
        if (k < kept) {
            o[0] = kx1[k]; o[1] = ky1[k]; o[2] = kx2[k]; o[3] = ky2[k];
            o[4] = ksc[k];
        } else {
            o[0] = 0.0f; o[1] = 0.0f; o[2] = 0.0f;
            o[3] = 0.0f; o[4] = 0.0f; o[5] = 0.0f;
        }
    }

    // ---- labels: 3 rows per warp batched for MLP, argmax over 80 classes ----
    for (int r0 = warp; r0 < kept; r0 += 96) {
        float vals[3][3];
        bool valid[3];
        #pragma unroll
        for (int g = 0; g < 3; g++) {
            int rI = r0 + 32 * g;
            bool v = rI < kept;
            valid[g] = v;
            int p = v ? kp[rI] : 0;
            int a = p % A;
            int hw = p / A;
            const float* bp = cls + (size_t)((n * A + a) * C) * HW + (size_t)hw;
            #pragma unroll
            for (int cc = 0; cc < 3; cc++) {
                int cidx = lane + 32 * cc;
                vals[g][cc] = (v && cidx < C) ? __ldg(bp + (size_t)cidx * HW)
                                              : -INFINITY;
            }
        }
        #pragma unroll
        for (int g = 0; g < 3; g++) {
            if (!valid[g]) break;
            float best = -INFINITY;
            int bc = 0;
            #pragma unroll
            for (int cc = 0; cc < 3; cc++) {
                int cidx = lane + 32 * cc;
                if (vals[g][cc] > best) { best = vals[g][cc]; bc = cidx; }
            }
            #pragma unroll
            for (int off = 16; off; off >>= 1) {
                float ov = __shfl_xor_sync(0xFFFFFFFFu, best, off);
                int   oc = __shfl_xor_sync(0xFFFFFFFFu, bc, off);
                if (ov > best || (ov == best && oc < bc)) { best = ov; bc = oc; }
            }
            if (lane == 0)
                out[(size_t)(n * KEEP + r0 + 32 * g) * 6 + 5] = (float)(bc + 1);
        }
    }
}

}  // namespace yolo

// ============================================================================
extern "C" void kernel_launch(void* const* d_in, const int* in_sizes, int n_in,
                              void* d_out, int out_size) {
    using namespace yolo;
    const float* anchors = (const float*)d_in[0];   // [16, 76800, 4]
    const float* obj     = (const float*)d_in[1];   // [16, 3, 160, 160]
    const float* reg     = (const float*)d_in[2];   // [16, 12, 160, 160]
    const float* cls     = (const float*)d_in[3];   // [16, 240, 160, 160]
    float* out = (float*)d_out;                     // [16, 300, 6]

    const int MEGA_SMEM = TOPK * (int)sizeof(u64)       // 32768
                        + TOPK * 5 * (int)sizeof(float) // 81920
                        + 304 * 7 * 4                   // 8512
                        + 128 * 4 + 128 * 16;           // 2560  => 125760

    cudaFuncSetAttribute(k_mega, cudaFuncAttributeMaxDynamicSharedMemorySize,
                         MEGA_SMEM);

    k_hist<<<dim3(NCHUNK, NBATCH), 512>>>(obj);
    k_compact<<<dim3(NCHUNK, NBATCH), 512>>>(obj, anchors, reg);
    k_mega<<<NBATCH, 1024, MEGA_SMEM>>>(cls, out);
}